// round 14
// baseline (speedup 1.0000x reference)
#include <cuda_runtime.h>
#include <cuda_fp16.h>
#include <stdint.h>

#define EPSF 1e-5f

#define S_K   65536.0f
#define S_IN  524288.0f
#define S_GI  (1.0f/524288.0f)
#define S_GO  2097152.0f
#define S_OUT (1.0f/2097152.0f)

static __device__ __forceinline__ float gelu_exact(float x){
    return 0.5f * x * (1.0f + erff(x * 0.70710678118654752440f));
}
static __device__ __forceinline__ void split16(float v, __half& h, __half& l){
    h = __float2half_rn(v);
    l = __float2half_rn(v - __half2float(h));
}
static __device__ __forceinline__ uint32_t packh(__half a, __half b){
    return (uint32_t)__half_as_ushort(a) | ((uint32_t)__half_as_ushort(b)<<16);
}

// ------------------------------------------------------------------
// static streams/events
// ------------------------------------------------------------------
struct GpuRes {
    cudaStream_t sA, sB, sC;
    cudaEvent_t evF, evLn, evQ, evV[4], evAX[4], evAYd;
    GpuRes(){
        cudaStreamCreateWithFlags(&sA, cudaStreamNonBlocking);
        cudaStreamCreateWithFlags(&sB, cudaStreamNonBlocking);
        cudaStreamCreateWithFlags(&sC, cudaStreamNonBlocking);
        cudaEventCreateWithFlags(&evF,   cudaEventDisableTiming);
        cudaEventCreateWithFlags(&evLn,  cudaEventDisableTiming);
        cudaEventCreateWithFlags(&evQ,   cudaEventDisableTiming);
        cudaEventCreateWithFlags(&evAYd, cudaEventDisableTiming);
        for (int i = 0; i < 4; ++i){
            cudaEventCreateWithFlags(&evV[i],  cudaEventDisableTiming);
            cudaEventCreateWithFlags(&evAX[i], cudaEventDisableTiming);
        }
    }
};
static GpuRes g_res;

// ------------------------------------------------------------------
// scratch (device globals)
// ------------------------------------------------------------------
__device__ __align__(16) __half g_unh [8388608];
__device__ __align__(16) __half g_unl [8388608];
__device__ __align__(16) __half g_vph [33554432];
__device__ __align__(16) __half g_t1h [33554432];
__device__ __align__(16) __half g_t2s [33554432];
__device__ __align__(16) __half g_goh [8388608];
__device__ __align__(16) __half g_gol [8388608];
__device__ __align__(16) __half g_wvh [65536];
__device__ __align__(16) __half g_wo1h[65536];
__device__ __align__(16) __half g_wo2h[16384];
__device__ __align__(16) float  g_sums [1024];
__device__ __align__(16) float g_mx [65536];
__device__ __align__(16) float g_my [65536];
__device__ __align__(16) float g_ux [32768];
__device__ __align__(16) float g_uy [32768];
__device__ __align__(16) float g_qx [786432];
__device__ __align__(16) float g_kxv[786432];
__device__ __align__(16) float g_qy [786432];
__device__ __align__(16) float g_kyv[786432];
__device__ __align__(16) __half g_kxmh[524288], g_kxml[524288];
__device__ __align__(16) __half g_kymh[524288], g_kyml[524288];

// ------------------------------------------------------------------
// PTX helpers
// ------------------------------------------------------------------
static __device__ __forceinline__ uint32_t s2u(const void* p){
    uint32_t a;
    asm("{ .reg .u64 t; cvta.to.shared.u64 t, %1; cvt.u32.u64 %0, t; }" : "=r"(a) : "l"(p));
    return a;
}
static __device__ __forceinline__ void cpa16(uint32_t s, const void* g){
    asm volatile("cp.async.cg.shared.global [%0], [%1], 16;" :: "r"(s), "l"(g));
}
static __device__ __forceinline__ void ldsm4(uint32_t* r, uint32_t addr){
    asm volatile("ldmatrix.sync.aligned.m8n8.x4.shared.b16 {%0,%1,%2,%3}, [%4];"
        : "=r"(r[0]),"=r"(r[1]),"=r"(r[2]),"=r"(r[3]) : "r"(addr));
}
static __device__ __forceinline__ void ldsm4t(uint32_t* r, uint32_t addr){
    asm volatile("ldmatrix.sync.aligned.m8n8.x4.trans.shared.b16 {%0,%1,%2,%3}, [%4];"
        : "=r"(r[0]),"=r"(r[1]),"=r"(r[2]),"=r"(r[3]) : "r"(addr));
}
static __device__ __forceinline__ void mma16816(float* c, const uint32_t* a, const uint32_t* b){
    asm volatile("mma.sync.aligned.m16n8k16.row.col.f32.f16.f16.f32 "
        "{%0,%1,%2,%3}, {%4,%5,%6,%7}, {%8,%9}, {%0,%1,%2,%3};"
        : "+f"(c[0]),"+f"(c[1]),"+f"(c[2]),"+f"(c[3])
        : "r"(a[0]),"r"(a[1]),"r"(a[2]),"r"(a[3]), "r"(b[0]),"r"(b[1]));
}

// ------------------------------------------------------------------
// fp16 2-term split MMA GEMM, 3-stage pipeline (unchanged from R13).
// ------------------------------------------------------------------
#define APB   6144
#define BPB   4352
#define STAGE (2*APB + BPB)
#define SMEMB (3*STAGE)

template<int AMODE, int BZMODE, int EPI>
__global__ void __launch_bounds__(256,2) mma_kernel(
    const __half* __restrict__ Ahi, const __half* __restrict__ Alo,
    const __half* __restrict__ Bhi,
    void* __restrict__ C0, void* __restrict__ C1,
    float* __restrict__ sums,
    int K, int KS, int NS, int ldc,
    long long Az, long long Bz, long long Cz,
    float iscale, float oscale)
{
    extern __shared__ __align__(16) char smem[];
    const uint32_t sb = s2u(smem);
    const int tid  = threadIdx.x;
    const int lane = tid & 31;
    const int wid  = tid >> 5;
    const int rm   = (wid >> 1) * 32;
    const int cn   = (wid & 1) * 64;
    const int z    = blockIdx.z;
    const int n0   = blockIdx.x * 128;
    const int m0   = blockIdx.y * 128;

    size_t zA = (size_t)z * (size_t)Az;
    size_t zB;
    if (BZMODE == 0) zB = (size_t)z * (size_t)Bz;
    else             zB = (size_t)(z >> 3) * 8388608ull + (size_t)(z & 7) * 64ull;

    const __half* gA[2]; uint32_t sAo[2];
    const __half* gA1 = nullptr;
    uint32_t sA1 = 0;
    float2 stv = make_float2(0.f, 1.f);
    uint4 ra;
    if (AMODE == 0){
        #pragma unroll
        for (int i = 0; i < 2; ++i){
            int c = tid + 256*i;
            int plane = c >> 8, row = (c >> 1) & 127, half = c & 1;
            gA[i] = (plane ? Alo : Ahi) + zA + (size_t)(m0 + row) * (size_t)K + half*8;
            sAo[i] = plane*APB + row*48 + half*16;
        }
    } else {
        float S  = sums[2*blockIdx.y];
        float S2 = sums[2*blockIdx.y + 1];
        float m  = S * (1.0f/65536.0f);
        float var_s = S2 * (1.0f/65536.0f) - m*m;
        stv = make_float2(m, rsqrtf(var_s * 0x1p-64f + EPSF) * (0x1p-32f * S_IN));
        int row = tid >> 1, half = tid & 1;
        gA1 = Ahi + zA + (size_t)(m0 + row) * (size_t)K + half*8;
        sA1 = row*48 + half*16;
    }
    const __half* gB; uint32_t sBo;
    {
        int row = tid >> 4, ch = tid & 15;
        gB = Bhi + zB + (size_t)row * (size_t)KS
           + (size_t)((n0 >> 6) + (ch >> 3)) * (size_t)NS + (ch & 7)*8;
        sBo = 2*APB + row*272 + ch*16;
    }

    const int NIT = K >> 4;

    auto store_norm = [&](int sbyte){
        const __half2* hp = (const __half2*)&ra;
        uint4 H, L;
        uint32_t* Hp = (uint32_t*)&H;
        uint32_t* Lp = (uint32_t*)&L;
        #pragma unroll
        for (int j = 0; j < 4; ++j){
            float2 f = __half22float2(hp[j]);
            float v0 = (f.x - stv.x) * stv.y;
            float v1 = (f.y - stv.x) * stv.y;
            __half h0,l0,h1,l1;
            split16(v0,h0,l0); split16(v1,h1,l1);
            Hp[j] = packh(h0,h1);
            Lp[j] = packh(l0,l1);
        }
        *(uint4*)(smem + sbyte + sA1)       = H;
        *(uint4*)(smem + sbyte + APB + sA1) = L;
    };

    if (AMODE == 0){
        #pragma unroll
        for (int s = 0; s < 2; ++s){
            uint32_t base = sb + s*STAGE;
            size_t ka = (size_t)s * 16;
            #pragma unroll
            for (int i = 0; i < 2; ++i) cpa16(base + sAo[i], gA[i] + ka);
            cpa16(base + sBo, gB + ka * (size_t)KS);
            asm volatile("cp.async.commit_group;");
        }
    } else {
        ra = *(const uint4*)gA1;
        store_norm(0);
        ra = *(const uint4*)(gA1 + 16);
        cpa16(sb + sBo, gB);
        asm volatile("cp.async.commit_group;");
        cpa16(sb + STAGE + sBo, gB + 16 * (size_t)KS);
        asm volatile("cp.async.commit_group;");
    }

    float acc[2][8][4];
    #pragma unroll
    for (int a = 0; a < 2; ++a)
        #pragma unroll
        for (int b = 0; b < 8; ++b)
            #pragma unroll
            for (int c = 0; c < 4; ++c) acc[a][b][c] = 0.f;

    int stg = 0;
    for (int it = 0; it < NIT; ++it){
        if (it < NIT-1) asm volatile("cp.async.wait_group 1;" ::: "memory");
        else            asm volatile("cp.async.wait_group 0;" ::: "memory");
        __syncthreads();

        const uint32_t st = sb + stg * STAGE;
        uint32_t af[2][2][4];
        uint32_t bf[4][4];
        #pragma unroll
        for (int p = 0; p < 2; ++p){
            uint32_t ab = st + p*APB;
            #pragma unroll
            for (int mi = 0; mi < 2; ++mi)
                ldsm4(af[p][mi], ab + (rm + mi*16 + (lane & 15))*48 + (lane >> 4)*16);
        }
        {
            uint32_t bb = st + 2*APB;
            #pragma unroll
            for (int nj = 0; nj < 4; ++nj)
                ldsm4t(bf[nj], bb + (lane & 15)*272 + (cn + nj*16 + (lane >> 4)*8)*2);
        }

        if (AMODE == 1){
            if (it + 1 < NIT){
                int ns = stg + 1; if (ns >= 3) ns -= 3;
                store_norm(ns * STAGE);
            }
            if (it + 2 < NIT){
                int ps = stg + 2; if (ps >= 3) ps -= 3;
                ra = *(const uint4*)(gA1 + (size_t)(it + 2) * 16);
                cpa16(sb + ps*STAGE + sBo, gB + (size_t)(it + 2) * 16 * (size_t)KS);
                asm volatile("cp.async.commit_group;");
            }
        } else {
            if (it + 2 < NIT){
                int ps = stg + 2; if (ps >= 3) ps -= 3;
                uint32_t base = sb + ps * STAGE;
                size_t ka = (size_t)(it + 2) * 16;
                #pragma unroll
                for (int i = 0; i < 2; ++i) cpa16(base + sAo[i], gA[i] + ka);
                cpa16(base + sBo, gB + ka * (size_t)KS);
                asm volatile("cp.async.commit_group;");
            }
        }

        #pragma unroll
        for (int mi = 0; mi < 2; ++mi){
            #pragma unroll
            for (int nj = 0; nj < 4; ++nj){
                #pragma unroll
                for (int blk = 0; blk < 2; ++blk){
                    float* d = acc[mi][nj*2 + blk];
                    mma16816(d, af[0][mi], &bf[nj][blk*2]);
                    mma16816(d, af[1][mi], &bf[nj][blk*2]);
                }
            }
        }
        if (++stg == 3) stg = 0;
    }

    const int gr = lane >> 2, tc = lane & 3;

    if (EPI == 3){
        float s = 0.f, s2 = 0.f;
        #pragma unroll
        for (int mi = 0; mi < 2; ++mi)
            #pragma unroll
            for (int n8 = 0; n8 < 8; ++n8)
                #pragma unroll
                for (int e = 0; e < 4; ++e){
                    float v = acc[mi][n8][e];
                    s += v; s2 += v*v;
                }
        #pragma unroll
        for (int o = 16; o; o >>= 1){
            s  += __shfl_xor_sync(0xffffffffu, s,  o);
            s2 += __shfl_xor_sync(0xffffffffu, s2, o);
        }
        if (lane == 0){
            int bi = (z >> 3) * 128 + (n0 >> 6) + (cn >> 6);
            atomicAdd(&sums[bi*2],   s);
            atomicAdd(&sums[bi*2+1], s2);
        }
    }

    #pragma unroll
    for (int mi = 0; mi < 2; ++mi){
        int r0 = m0 + rm + mi*16 + gr;
        #pragma unroll
        for (int n8 = 0; n8 < 8; ++n8){
            float* d = acc[mi][n8];
            int col = n0 + cn + n8*8 + tc*2;
            if (EPI == 0){
                __half* Ch = (__half*)C0;
                size_t zc = (size_t)z * (size_t)Cz;
                size_t o0 = zc + (size_t)r0*ldc + col;
                size_t o1 = zc + (size_t)(r0+8)*ldc + col;
                *(__half2*)(Ch + o0) = __halves2half2(__float2half_rn(d[0]), __float2half_rn(d[1]));
                *(__half2*)(Ch + o1) = __halves2half2(__float2half_rn(d[2]), __float2half_rn(d[3]));
            } else if (EPI == 1){
                __half* Ch = (__half*)C0;
                __half* Cl = (__half*)C1;
                size_t zc = (size_t)z * (size_t)Cz;
                float v0 = gelu_exact(d[0]*iscale)*oscale;
                float v1 = gelu_exact(d[1]*iscale)*oscale;
                float v2 = gelu_exact(d[2]*iscale)*oscale;
                float v3 = gelu_exact(d[3]*iscale)*oscale;
                __half h0,l0,h1,l1,h2,l2,h3,l3;
                split16(v0,h0,l0); split16(v1,h1,l1);
                split16(v2,h2,l2); split16(v3,h3,l3);
                size_t o0 = zc + (size_t)r0*ldc + col;
                size_t o1 = zc + (size_t)(r0+8)*ldc + col;
                *(__half2*)(Ch + o0) = __halves2half2(h0, h1);
                *(__half2*)(Cl + o0) = __halves2half2(l0, l1);
                *(__half2*)(Ch + o1) = __halves2half2(h2, h3);
                *(__half2*)(Cl + o1) = __halves2half2(l2, l3);
            } else if (EPI == 2){
                float* Cf = (float*)C0;
                size_t zc = (size_t)z * (size_t)Cz;
                float2 w0; w0.x = d[0]*oscale; w0.y = d[1]*oscale;
                float2 w1; w1.x = d[2]*oscale; w1.y = d[3]*oscale;
                *(float2*)(Cf + zc + (size_t)r0*ldc + col) = w0;
                *(float2*)(Cf + zc + (size_t)(r0+8)*ldc + col) = w1;
            } else {
                __half* Ch = (__half*)C0;
                size_t zb = (size_t)(z >> 3) * 8388608ull + (size_t)(z & 7) * 64ull;
                size_t o = zb + (size_t)(col >> 6)*65536 + (col & 63);
                *(__half2*)(Ch + o + (size_t)r0*512)
                    = __halves2half2(__float2half_rn(d[0]), __float2half_rn(d[1]));
                *(__half2*)(Ch + o + (size_t)(r0+8)*512)
                    = __halves2half2(__float2half_rn(d[2]), __float2half_rn(d[3]));
            }
        }
    }
}

// ------------------------------------------------------------------
// elementwise kernels
// ------------------------------------------------------------------
__global__ void ln_kernel(const float* __restrict__ u, const float* __restrict__ g,
                          const float* __restrict__ b,
                          __half* __restrict__ oh, __half* __restrict__ ol){
    int w = threadIdx.x >> 5, lane = threadIdx.x & 31;
    size_t row = (size_t)blockIdx.x * 8 + w;
    float4 v = *((const float4*)(u + row*128) + lane);
    float s = v.x + v.y + v.z + v.w;
    #pragma unroll
    for(int o=16;o;o>>=1) s += __shfl_xor_sync(0xffffffffu, s, o);
    float m = s * (1.0f/128.0f);
    float d0=v.x-m, d1=v.y-m, d2=v.z-m, d3=v.w-m;
    float q = d0*d0 + d1*d1 + d2*d2 + d3*d3;
    #pragma unroll
    for(int o=16;o;o>>=1) q += __shfl_xor_sync(0xffffffffu, q, o);
    float inv = rsqrtf(q * (1.0f/128.0f) + EPSF);
    float4 gg = *((const float4*)g + lane);
    float4 bb = *((const float4*)b + lane);
    float r0 = d0*inv*gg.x + bb.x;
    float r1 = d1*inv*gg.y + bb.y;
    float r2 = d2*inv*gg.z + bb.z;
    float r3 = d3*inv*gg.w + bb.w;
    __half h0,l0,h1,l1,h2,l2,h3,l3;
    split16(r0,h0,l0); split16(r1,h1,l1); split16(r2,h2,l2); split16(r3,h3,l3);
    uint2 H; H.x = packh(h0,h1); H.y = packh(h2,h3);
    uint2 L; L.x = packh(l0,l1); L.y = packh(l2,l3);
    *(uint2*)(oh + row*128 + lane*4) = H;
    *(uint2*)(ol + row*128 + lane*4) = L;
}

// means read hi plane only
__global__ void mean_y_kernel(const __half* __restrict__ uh, float* __restrict__ mx){
    int bx = blockIdx.x; int d = threadIdx.x;
    size_t base = (size_t)bx*16384 + d;
    float s = 0.f;
    #pragma unroll 8
    for(int y=0;y<128;y++) s += __half2float(uh[base + (size_t)y*128]);
    mx[(size_t)bx*128 + d] = s * (1.0f/128.0f);
}
__global__ void mean_x_kernel(const __half* __restrict__ uh, float* __restrict__ my){
    int b = blockIdx.x >> 7, y = blockIdx.x & 127; int d = threadIdx.x;
    size_t base = (size_t)b*2097152 + (size_t)y*128 + d;
    float s = 0.f;
    #pragma unroll 8
    for(int x=0;x<128;x++) s += __half2float(uh[base + (size_t)x*16384]);
    my[(size_t)blockIdx.x*128 + d] = s * (1.0f/128.0f);
}

// pooling reducer v5: 1 row/block, 512 blocks, 512 threads, deep split-k
__global__ void __launch_bounds__(512) pool_kernel(const float* __restrict__ mrow,
    const float* __restrict__ Win,  const float* __restrict__ pWin,
    const float* __restrict__ lg,   const float* __restrict__ lb,
    const float* __restrict__ W1,   const float* __restrict__ b1,
    const float* __restrict__ W2,   const float* __restrict__ b2,
    float* __restrict__ out)
{
    __shared__ float row[128], part[512], s2[128], h1[256], gt[128];
    int t = threadIdx.x;
    int R0 = blockIdx.x;
    if (t < 128) row[t] = mrow[(size_t)R0*128 + t];
    __syncthreads();
    // gemv1: 128 out, 4-way split-k (32 loads/thread)
    {
        int c = t & 127, kh = (t >> 7) * 32;
        float a0=0,a1=0;
        #pragma unroll 8
        for (int k = 0; k < 16; ++k){
            a0 += row[kh+k]    * Win[(kh+k)*128 + c];
            a1 += row[kh+k+16] * Win[(kh+k+16)*128 + c];
        }
        part[t] = a0+a1;
    }
    __syncthreads();
    if (t < 128) row[t] = (part[t] + part[t+128]) + (part[t+256] + part[t+384]);
    __syncthreads();
    // gemv2
    {
        int c = t & 127, kh = (t >> 7) * 32;
        float a0=0,a1=0;
        #pragma unroll 8
        for (int k = 0; k < 16; ++k){
            a0 += row[kh+k]    * pWin[(kh+k)*128 + c];
            a1 += row[kh+k+16] * pWin[(kh+k+16)*128 + c];
        }
        part[t] = a0+a1;
    }
    __syncthreads();
    if (t < 128) s2[t] = (part[t] + part[t+128]) + (part[t+256] + part[t+384]);
    __syncthreads();
    // layernorm on s2 (warp 0)
    if (t < 32){
        float x0 = s2[t], x1 = s2[t+32], x2 = s2[t+64], x3 = s2[t+96];
        float s = x0+x1+x2+x3;
        float q = x0*x0+x1*x1+x2*x2+x3*x3;
        #pragma unroll
        for(int o=16;o;o>>=1){ s += __shfl_xor_sync(0xffffffffu,s,o); q += __shfl_xor_sync(0xffffffffu,q,o); }
        float m = s * (1.0f/128.0f);
        float var = q * (1.0f/128.0f) - m*m;
        float inv = rsqrtf(var + EPSF);
        s2[t]    = (x0-m)*inv*lg[t]    + lb[t];
        s2[t+32] = (x1-m)*inv*lg[t+32] + lb[t+32];
        s2[t+64] = (x2-m)*inv*lg[t+64] + lb[t+64];
        s2[t+96] = (x3-m)*inv*lg[t+96] + lb[t+96];
    }
    __syncthreads();
    // gemv3: 256 out, 2-way split-k (64 loads/thread, 4-way ILP)
    {
        int c = t & 255, kh = (t >> 8) * 64;
        float a0=0,a1=0,a2=0,a3=0;
        #pragma unroll 8
        for (int k = 0; k < 16; ++k){
            a0 += s2[kh+k]    * W1[(kh+k)*256 + c];
            a1 += s2[kh+k+16] * W1[(kh+k+16)*256 + c];
            a2 += s2[kh+k+32] * W1[(kh+k+32)*256 + c];
            a3 += s2[kh+k+48] * W1[(kh+k+48)*256 + c];
        }
        part[t] = (a0+a1)+(a2+a3);
    }
    __syncthreads();
    if (t < 256) h1[t] = b1[t] + part[t] + part[t+256];
    __syncthreads();
    if (t < 128) gt[t] = gelu_exact(h1[t]) * h1[128 + t];
    __syncthreads();
    // gemv4: 64 out, 8-way split-k (16 loads/thread)
    {
        int c = t & 63, kh = (t >> 6) * 16;
        float a0=0,a1=0;
        #pragma unroll 8
        for (int k = 0; k < 8; ++k){
            a0 += gt[kh+k]   * W2[(kh+k)*64 + c];
            a1 += gt[kh+k+8] * W2[(kh+k+8)*64 + c];
        }
        part[t] = a0+a1;
    }
    __syncthreads();
    if (t < 64){
        float s = b2[t];
        #pragma unroll
        for (int j = 0; j < 8; ++j) s += part[t + 64*j];
        out[(size_t)R0*64 + t] = s;
    }
}

// qk projection + rotary (unchanged)
__global__ void qkrot_kernel(const float* __restrict__ uu,
    const float* __restrict__ Wqk, const float* __restrict__ pos,
    float* __restrict__ qo, float* __restrict__ ko)
{
    __shared__ float r[8][64];
    __shared__ float invf[96];
    __shared__ float pp[8];
    __shared__ float qs[8][192], ks[8][192];
    int t = threadIdx.x;
    int rb = blockIdx.x >> 3, h = blockIdx.x & 7;
    int R0 = rb * 8;
    int b = R0 >> 7;
    {
        int row = t >> 6, k = t & 63;
        r[row][k]   = uu[(size_t)(R0 + row)*64 + k];
        r[row+4][k] = uu[(size_t)(R0 + row + 4)*64 + k];
    }
    if (t < 96) invf[t] = powf(10000.0f, -(float)t*(1.0f/96.0f));
    if (t < 8)  pp[t] = pos[(R0 + t) & 127] * 64.0f;
    __syncthreads();
    for (int col = t; col < 384; col += 256){
        int which = col >= 192;
        int c = col - which*192;
        const float* w = Wqk + (size_t)which*1536 + h*192 + c;
        float a0=0,a1=0,a2=0,a3=0,a4=0,a5=0,a6=0,a7=0;
        #pragma unroll 8
        for (int k = 0; k < 64; ++k){
            float wv = w[(size_t)k*3072];
            a0 += r[0][k]*wv; a1 += r[1][k]*wv; a2 += r[2][k]*wv; a3 += r[3][k]*wv;
            a4 += r[4][k]*wv; a5 += r[5][k]*wv; a6 += r[6][k]*wv; a7 += r[7][k]*wv;
        }
        float* dst = which ? &ks[0][0] : &qs[0][0];
        dst[0*192+c]=a0; dst[1*192+c]=a1; dst[2*192+c]=a2; dst[3*192+c]=a3;
        dst[4*192+c]=a4; dst[5*192+c]=a5; dst[6*192+c]=a6; dst[7*192+c]=a7;
    }
    __syncthreads();
    for (int i = t; i < 1536; i += 256){
        int row = i / 192, c = i - row*192;
        int j = (c < 96) ? c : c - 96;
        float f = pp[row] * invf[j];
        float cs = cosf(f), sn = sinf(f);
        float q2, k2;
        if (c < 96){
            q2 = qs[row][c]*cs - qs[row][c+96]*sn;
            k2 = ks[row][c]*cs - ks[row][c+96]*sn;
        } else {
            q2 = qs[row][c]*cs + qs[row][c-96]*sn;
            k2 = ks[row][c]*cs + ks[row][c-96]*sn;
        }
        int n = (R0 + row) & 127;
        size_t idx = ((size_t)(b*8 + h)*128 + n)*192 + c;
        qo[idx] = q2; ko[idx] = k2;
    }
}

__global__ void quant3_kernel(const float* __restrict__ Wv, const float* __restrict__ Wo1,
                              const float* __restrict__ Wo2,
                              __half* __restrict__ wvh, __half* __restrict__ wo1h,
                              __half* __restrict__ wo2h){
    int i = blockIdx.x*256 + threadIdx.x;
    if (i < 65536)       wvh[i]          = __float2half_rn(Wv[i]);
    else if (i < 131072) wo1h[i-65536]   = __float2half_rn(Wo1[i-65536]);
    else if (i < 147456) wo2h[i-131072]  = __float2half_rn(Wo2[i-131072]);
}

// ---------------- fp32 sgemm for kx/ky (K=192, TRANSB), split epilogue ----------------
__global__ void __launch_bounds__(256) sgemm_tb_kernel(
    const float* __restrict__ Ag, const float* __restrict__ Bg,
    __half* __restrict__ Ch, __half* __restrict__ Cl,
    int K, int lda, int ldb, int ldc,
    long long bsA, long long bsB, long long bsC, float scale)
{
    const int z = blockIdx.z;
    const float* A = Ag + (size_t)z * (size_t)bsA;
    const float* B = Bg + (size_t)z * (size_t)bsB;
    const int m0 = blockIdx.y*64, n0 = blockIdx.x*64;
    const int tid = threadIdx.x;
    const int tx = tid & 15, ty = tid >> 4;
    __shared__ float As[16][64];
    __shared__ float Bs[16][64];
    float acc[4][4];
    #pragma unroll
    for(int i=0;i<4;i++)
        #pragma unroll
        for(int j=0;j<4;j++) acc[i][j]=0.f;
    const int arow = tid>>2, ac4 = (tid&3)*4;
    const int tcol = tid>>2, tr4 = (tid&3)*4;
    for(int k0=0;k0<K;k0+=16){
        float4 av = *(const float4*)(A + (size_t)(m0+arow)*lda + (k0+ac4));
        As[ac4+0][arow]=av.x; As[ac4+1][arow]=av.y; As[ac4+2][arow]=av.z; As[ac4+3][arow]=av.w;
        float4 bv = *(const float4*)(B + (size_t)(n0+tcol)*ldb + (k0+tr4));
        Bs[tr4+0][tcol]=bv.x; Bs[tr4+1][tcol]=bv.y; Bs[tr4+2][tcol]=bv.z; Bs[tr4+3][tcol]=bv.w;
        __syncthreads();
        #pragma unroll
        for(int k=0;k<16;k++){
            float4 a4 = *(const float4*)(&As[k][ty*4]);
            float4 b4 = *(const float4*)(&Bs[k][tx*4]);
            float a[4]={a4.x,a4.y,a4.z,a4.w};
            float bb[4]={b4.x,b4.y,b4.z,b4.w};
            #pragma unroll
            for(int i=0;i<4;i++)
                #pragma unroll
                for(int j=0;j<4;j++) acc[i][j] += a[i]*bb[j];
        }
        __syncthreads();
    }
    size_t zc = (size_t)z * (size_t)bsC;
    #pragma unroll
    for(int i=0;i<4;i++){
        int row = m0 + ty*4 + i;
        #pragma unroll
        for(int j=0;j<4;j+=2){
            int col = n0 + tx*4 + j;
            __half h0,l0,h1,l1;
            split16(acc[i][j]*scale,   h0, l0);
            split16(acc[i][j+1]*scale, h1, l1);
            size_t o = zc + (size_t)row*ldc + col;
            *(__half2*)(Ch + o) = __halves2half2(h0,h1);
            *(__half2*)(Cl + o) = __halves2half2(l0,l1);
        }
    }
}

// ------------------------------------------------------------------
// launch — per-batch pipelined GEMM chain on a multi-stream DAG
// ------------------------------------------------------------------
extern "C" void kernel_launch(void* const* d_in, const int* in_sizes, int n_in,
                              void* d_out, int out_size){
    const float* u      = (const float*)d_in[0];
    const float* pos_x  = (const float*)d_in[1];
    const float* pos_y  = (const float*)d_in[2];
    const float* ln_g   = (const float*)d_in[3];
    const float* ln_b   = (const float*)d_in[4];
    const float* Wv     = (const float*)d_in[5];
    const float* Win    = (const float*)d_in[6];
    const float* px_Win = (const float*)d_in[7];
    const float* px_g   = (const float*)d_in[8];
    const float* px_b   = (const float*)d_in[9];
    const float* px_W1  = (const float*)d_in[10];
    const float* px_b1  = (const float*)d_in[11];
    const float* px_W2  = (const float*)d_in[12];
    const float* px_b2  = (const float*)d_in[13];
    const float* py_Win = (const float*)d_in[14];
    const float* py_g   = (const float*)d_in[15];
    const float* py_b   = (const float*)d_in[16];
    const float* py_W1  = (const float*)d_in[17];
    const float* py_b1  = (const float*)d_in[18];
    const float* py_W2  = (const float*)d_in[19];
    const float* py_b2  = (const float*)d_in[20];
    const float* Wqk_x  = (const float*)d_in[21];
    const float* Wqk_y  = (const float*)d_in[22];
    const float* Wo1    = (const float*)d_in[23];
    const float* Wo2    = (const float*)d_in[24];
    float* out = (float*)d_out;

    __half *unh,*unl,*vph,*t1h,*t2s,*goh,*gol;
    __half *wvh,*wo1h,*wo2h,*kxmh,*kxml,*kymh,*kyml;
    float *mx,*my,*ux,*uy,*qx,*kxv,*qy,*kyv,*sums;
    cudaGetSymbolAddress((void**)&unh, g_unh);  cudaGetSymbolAddress((void**)&unl, g_unl);
    cudaGetSymbolAddress((void**)&vph, g_vph);
    cudaGetSymbolAddress((void**)&t1h, g_t1h);
    cudaGetSymbolAddress((void**)&t2s, g_t2s);
    cudaGetSymbolAddress((void**)&goh, g_goh);  cudaGetSymbolAddress((void**)&gol, g_gol);
    cudaGetSymbolAddress((void**)&wvh, g_wvh);
    cudaGetSymbolAddress((void**)&wo1h,g_wo1h);
    cudaGetSymbolAddress((void**)&wo2h,g_wo2h);
    cudaGetSymbolAddress((void**)&kxmh,g_kxmh); cudaGetSymbolAddress((void**)&kxml,g_kxml);
    cudaGetSymbolAddress((void**)&kymh,g_kymh); cudaGetSymbolAddress((void**)&kyml,g_kyml);
    cudaGetSymbolAddress((void**)&mx,  g_mx);   cudaGetSymbolAddress((void**)&my,  g_my);
    cudaGetSymbolAddress((void**)&ux,  g_ux);   cudaGetSymbolAddress((void**)&uy,  g_uy);
    cudaGetSymbolAddress((void**)&qx,  g_qx);   cudaGetSymbolAddress((void**)&kxv, g_kxv);
    cudaGetSymbolAddress((void**)&qy,  g_qy);   cudaGetSymbolAddress((void**)&kyv, g_kyv);
    cudaGetSymbolAddress((void**)&sums, g_sums);

    cudaFuncSetAttribute(mma_kernel<0,0,0>, cudaFuncAttributeMaxDynamicSharedMemorySize, SMEMB);
    cudaFuncSetAttribute(mma_kernel<0,1,0>, cudaFuncAttributeMaxDynamicSharedMemorySize, SMEMB);
    cudaFuncSetAttribute(mma_kernel<0,0,3>, cudaFuncAttributeMaxDynamicSharedMemorySize, SMEMB);
    cudaFuncSetAttribute(mma_kernel<1,0,1>, cudaFuncAttributeMaxDynamicSharedMemorySize, SMEMB);
    cudaFuncSetAttribute(mma_kernel<0,0,2>, cudaFuncAttributeMaxDynamicSharedMemorySize, SMEMB);

    cudaStream_t sA = g_res.sA, sB = g_res.sB, sC = g_res.sC;

    // ---- fork ----
    cudaEventRecord(g_res.evF, 0);
    cudaStreamWaitEvent(sA, g_res.evF, 0);
    cudaStreamWaitEvent(sB, g_res.evF, 0);
    cudaStreamWaitEvent(sC, g_res.evF, 0);

    quant3_kernel<<<576,256,0,sC>>>(Wv, Wo1, Wo2, wvh, wo1h, wo2h);
    cudaEventRecord(g_res.evQ, sC);
    cudaMemsetAsync(sums, 0, 1024*sizeof(float), sB);

    // ---- main: ln ----
    ln_kernel<<<8192,256,0,0>>>(u, ln_g, ln_b, unh, unl);
    cudaEventRecord(g_res.evLn, 0);

    // ---- branch A (x-chain) on sA ----
    cudaStreamWaitEvent(sA, g_res.evLn, 0);
    mean_y_kernel<<<512,128,0,sA>>>(unh, mx);
    pool_kernel<<<512,512,0,sA>>>(mx, Win, px_Win, px_g, px_b, px_W1, px_b1, px_W2, px_b2, ux);
    qkrot_kernel<<<512,256,0,sA>>>(ux, Wqk_x, pos_x, qx, kxv);
    sgemm_tb_kernel<<<dim3(2,2,32),256,0,sA>>>(qx, kxv, kxmh, kxml, 192, 192, 192, 128,
                                               24576, 24576, 16384, S_K);

    // ---- branch B (y-chain) on sB ----
    cudaStreamWaitEvent(sB, g_res.evLn, 0);
    mean_x_kernel<<<512,128,0,sB>>>(unh, my);
    pool_kernel<<<512,512,0,sB>>>(my, Win, py_Win, py_g, py_b, py_W1, py_b1, py_W2, py_b2, uy);
    qkrot_kernel<<<512,256,0,sB>>>(uy, Wqk_y, pos_y, qy, kyv);
    sgemm_tb_kernel<<<dim3(2,2,32),256,0,sB>>>(qy, kyv, kymh, kyml, 192, 192, 192, 128,
                                               24576, 24576, 16384, S_K);

    // ---- main: v-GEMM in 4 per-batch quarters ----
    cudaStreamWaitEvent(0, g_res.evQ, 0);
    for (int q = 0; q < 4; ++q){
        mma_kernel<0,0,0><<<dim3(4,128,1),256,SMEMB,0>>>(
            unh + (size_t)q*2097152, unl + (size_t)q*2097152, wvh,
            vph + (size_t)q*8388608, nullptr, nullptr,
            128, 512, 64, 512, 0, 0, 0, 1.0f, 1.0f);
        cudaEventRecord(g_res.evV[q], 0);
    }

    // ---- attend-x quarters on sA (after branch-A sgemm, stream-ordered) ----
    for (int q = 0; q < 4; ++q){
        cudaStreamWaitEvent(sA, g_res.evV[q], 0);
        mma_kernel<0,1,0><<<dim3(64,1,8),256,SMEMB,sA>>>(
            kxmh + (size_t)q*131072, kxml + (size_t)q*131072, vph + (size_t)q*8388608,
            t1h + (size_t)q*8388608, nullptr, nullptr,
            128, 65536, 512, 8192, 16384, 0, 1048576, 1.0f, 1.0f);
        cudaEventRecord(g_res.evAX[q], sA);
    }

    // ---- attend-y quarters on sB (after branch-B sgemm, stream-ordered) ----
    for (int q = 0; q < 4; ++q){
        cudaStreamWaitEvent(sB, g_res.evAX[q], 0);
        mma_kernel<0,0,3><<<dim3(64,1,8),256,SMEMB,sB>>>(
            kymh + (size_t)q*131072, kyml + (size_t)q*131072, t1h + (size_t)q*8388608,
            t2s + (size_t)q*8388608, nullptr, sums + (size_t)q*256,
            128, 64, 8192, 0, 16384, 1048576, 0, 1.0f, 1.0f);
    }
    cudaEventRecord(g_res.evAYd, sB);

    // ---- main: tail ----
    cudaStreamWaitEvent(0, g_res.evAYd, 0);
    mma_kernel<1,0,1><<<dim3(1,512,1),256,SMEMB,0>>>(t2s, nullptr, wo1h, goh, gol,
        sums, 512, 128, 64, 128, 0, 0, 0, S_GI, S_GO);
    mma_kernel<0,0,2><<<dim3(1,512,1),256,SMEMB,0>>>(goh, gol, wo2h, out, nullptr,
        nullptr, 128, 128, 64, 128, 0, 0, 0, 1.0f, S_OUT);
}

// round 15
// speedup vs baseline: 1.0218x; 1.0218x over previous
#include <cuda_runtime.h>
#include <cuda_fp16.h>
#include <stdint.h>

#define EPSF 1e-5f

#define S_K   65536.0f
#define S_IN  524288.0f
#define S_GI  (1.0f/524288.0f)
#define S_GO  2097152.0f
#define S_OUT (1.0f/2097152.0f)

static __device__ __forceinline__ float gelu_exact(float x){
    return 0.5f * x * (1.0f + erff(x * 0.70710678118654752440f));
}
static __device__ __forceinline__ void split16(float v, __half& h, __half& l){
    h = __float2half_rn(v);
    l = __float2half_rn(v - __half2float(h));
}
static __device__ __forceinline__ uint32_t packh(__half a, __half b){
    return (uint32_t)__half_as_ushort(a) | ((uint32_t)__half_as_ushort(b)<<16);
}

// ------------------------------------------------------------------
// static streams/events
// ------------------------------------------------------------------
struct GpuRes {
    cudaStream_t sA, sB, sC;
    cudaEvent_t evF, evLn, evQ, evX, evY;
    GpuRes(){
        cudaStreamCreateWithFlags(&sA, cudaStreamNonBlocking);
        cudaStreamCreateWithFlags(&sB, cudaStreamNonBlocking);
        cudaStreamCreateWithFlags(&sC, cudaStreamNonBlocking);
        cudaEventCreateWithFlags(&evF,  cudaEventDisableTiming);
        cudaEventCreateWithFlags(&evLn, cudaEventDisableTiming);
        cudaEventCreateWithFlags(&evQ,  cudaEventDisableTiming);
        cudaEventCreateWithFlags(&evX,  cudaEventDisableTiming);
        cudaEventCreateWithFlags(&evY,  cudaEventDisableTiming);
    }
};
static GpuRes g_res;

// ------------------------------------------------------------------
// scratch (device globals)
// ------------------------------------------------------------------
__device__ __align__(16) __half g_unh [8388608];
__device__ __align__(16) __half g_unl [8388608];
__device__ __align__(16) __half g_vph [33554432];
__device__ __align__(16) __half g_t1h [33554432];
__device__ __align__(16) __half g_t2s [33554432];
__device__ __align__(16) __half g_goh [8388608];
__device__ __align__(16) __half g_gol [8388608];
__device__ __align__(16) __half g_wvh [65536];
__device__ __align__(16) __half g_wo1h[65536];
__device__ __align__(16) __half g_wo2h[16384];
__device__ __align__(16) float  g_sums [1024];
__device__ __align__(16) float g_mx [65536];
__device__ __align__(16) float g_my [65536];
__device__ __align__(16) float g_ux [32768];
__device__ __align__(16) float g_uy [32768];
__device__ __align__(16) float g_qx [786432];
__device__ __align__(16) float g_kxv[786432];
__device__ __align__(16) float g_qy [786432];
__device__ __align__(16) float g_kyv[786432];
__device__ __align__(16) __half g_kxmh[524288], g_kxml[524288];
__device__ __align__(16) __half g_kymh[524288], g_kyml[524288];

// ------------------------------------------------------------------
// PTX helpers
// ------------------------------------------------------------------
static __device__ __forceinline__ uint32_t s2u(const void* p){
    uint32_t a;
    asm("{ .reg .u64 t; cvta.to.shared.u64 t, %1; cvt.u32.u64 %0, t; }" : "=r"(a) : "l"(p));
    return a;
}
static __device__ __forceinline__ void cpa16(uint32_t s, const void* g){
    asm volatile("cp.async.cg.shared.global [%0], [%1], 16;" :: "r"(s), "l"(g));
}
static __device__ __forceinline__ void ldsm4(uint32_t* r, uint32_t addr){
    asm volatile("ldmatrix.sync.aligned.m8n8.x4.shared.b16 {%0,%1,%2,%3}, [%4];"
        : "=r"(r[0]),"=r"(r[1]),"=r"(r[2]),"=r"(r[3]) : "r"(addr));
}
static __device__ __forceinline__ void ldsm4t(uint32_t* r, uint32_t addr){
    asm volatile("ldmatrix.sync.aligned.m8n8.x4.trans.shared.b16 {%0,%1,%2,%3}, [%4];"
        : "=r"(r[0]),"=r"(r[1]),"=r"(r[2]),"=r"(r[3]) : "r"(addr));
}
static __device__ __forceinline__ void mma16816(float* c, const uint32_t* a, const uint32_t* b){
    asm volatile("mma.sync.aligned.m16n8k16.row.col.f32.f16.f16.f32 "
        "{%0,%1,%2,%3}, {%4,%5,%6,%7}, {%8,%9}, {%0,%1,%2,%3};"
        : "+f"(c[0]),"+f"(c[1]),"+f"(c[2]),"+f"(c[3])
        : "r"(a[0]),"r"(a[1]),"r"(a[2]),"r"(a[3]), "r"(b[0]),"r"(b[1]));
}

// ------------------------------------------------------------------
// fp16 2-term split MMA GEMM, 3-stage pipeline (R13-proven, unchanged).
// ------------------------------------------------------------------
#define APB   6144
#define BPB   4352
#define STAGE (2*APB + BPB)
#define SMEMB (3*STAGE)

template<int AMODE, int BZMODE, int EPI>
__global__ void __launch_bounds__(256,2) mma_kernel(
    const __half* __restrict__ Ahi, const __half* __restrict__ Alo,
    const __half* __restrict__ Bhi,
    void* __restrict__ C0, void* __restrict__ C1,
    float* __restrict__ sums,
    int K, int KS, int NS, int ldc,
    long long Az, long long Bz, long long Cz,
    float iscale, float oscale)
{
    extern __shared__ __align__(16) char smem[];
    const uint32_t sb = s2u(smem);
    const int tid  = threadIdx.x;
    const int lane = tid & 31;
    const int wid  = tid >> 5;
    const int rm   = (wid >> 1) * 32;
    const int cn   = (wid & 1) * 64;
    const int z    = blockIdx.z;
    const int n0   = blockIdx.x * 128;
    const int m0   = blockIdx.y * 128;

    size_t zA = (size_t)z * (size_t)Az;
    size_t zB;
    if (BZMODE == 0) zB = (size_t)z * (size_t)Bz;
    else             zB = (size_t)(z >> 3) * 8388608ull + (size_t)(z & 7) * 64ull;

    const __half* gA[2]; uint32_t sAo[2];
    const __half* gA1 = nullptr;
    uint32_t sA1 = 0;
    float2 stv = make_float2(0.f, 1.f);
    uint4 ra;
    if (AMODE == 0){
        #pragma unroll
        for (int i = 0; i < 2; ++i){
            int c = tid + 256*i;
            int plane = c >> 8, row = (c >> 1) & 127, half = c & 1;
            gA[i] = (plane ? Alo : Ahi) + zA + (size_t)(m0 + row) * (size_t)K + half*8;
            sAo[i] = plane*APB + row*48 + half*16;
        }
    } else {
        float S  = sums[2*blockIdx.y];
        float S2 = sums[2*blockIdx.y + 1];
        float m  = S * (1.0f/65536.0f);
        float var_s = S2 * (1.0f/65536.0f) - m*m;
        stv = make_float2(m, rsqrtf(var_s * 0x1p-64f + EPSF) * (0x1p-32f * S_IN));
        int row = tid >> 1, half = tid & 1;
        gA1 = Ahi + zA + (size_t)(m0 + row) * (size_t)K + half*8;
        sA1 = row*48 + half*16;
    }
    const __half* gB; uint32_t sBo;
    {
        int row = tid >> 4, ch = tid & 15;
        gB = Bhi + zB + (size_t)row * (size_t)KS
           + (size_t)((n0 >> 6) + (ch >> 3)) * (size_t)NS + (ch & 7)*8;
        sBo = 2*APB + row*272 + ch*16;
    }

    const int NIT = K >> 4;

    auto store_norm = [&](int sbyte){
        const __half2* hp = (const __half2*)&ra;
        uint4 H, L;
        uint32_t* Hp = (uint32_t*)&H;
        uint32_t* Lp = (uint32_t*)&L;
        #pragma unroll
        for (int j = 0; j < 4; ++j){
            float2 f = __half22float2(hp[j]);
            float v0 = (f.x - stv.x) * stv.y;
            float v1 = (f.y - stv.x) * stv.y;
            __half h0,l0,h1,l1;
            split16(v0,h0,l0); split16(v1,h1,l1);
            Hp[j] = packh(h0,h1);
            Lp[j] = packh(l0,l1);
        }
        *(uint4*)(smem + sbyte + sA1)       = H;
        *(uint4*)(smem + sbyte + APB + sA1) = L;
    };

    if (AMODE == 0){
        #pragma unroll
        for (int s = 0; s < 2; ++s){
            uint32_t base = sb + s*STAGE;
            size_t ka = (size_t)s * 16;
            #pragma unroll
            for (int i = 0; i < 2; ++i) cpa16(base + sAo[i], gA[i] + ka);
            cpa16(base + sBo, gB + ka * (size_t)KS);
            asm volatile("cp.async.commit_group;");
        }
    } else {
        ra = *(const uint4*)gA1;
        store_norm(0);
        ra = *(const uint4*)(gA1 + 16);
        cpa16(sb + sBo, gB);
        asm volatile("cp.async.commit_group;");
        cpa16(sb + STAGE + sBo, gB + 16 * (size_t)KS);
        asm volatile("cp.async.commit_group;");
    }

    float acc[2][8][4];
    #pragma unroll
    for (int a = 0; a < 2; ++a)
        #pragma unroll
        for (int b = 0; b < 8; ++b)
            #pragma unroll
            for (int c = 0; c < 4; ++c) acc[a][b][c] = 0.f;

    int stg = 0;
    for (int it = 0; it < NIT; ++it){
        if (it < NIT-1) asm volatile("cp.async.wait_group 1;" ::: "memory");
        else            asm volatile("cp.async.wait_group 0;" ::: "memory");
        __syncthreads();

        const uint32_t st = sb + stg * STAGE;
        uint32_t af[2][2][4];
        uint32_t bf[4][4];
        #pragma unroll
        for (int p = 0; p < 2; ++p){
            uint32_t ab = st + p*APB;
            #pragma unroll
            for (int mi = 0; mi < 2; ++mi)
                ldsm4(af[p][mi], ab + (rm + mi*16 + (lane & 15))*48 + (lane >> 4)*16);
        }
        {
            uint32_t bb = st + 2*APB;
            #pragma unroll
            for (int nj = 0; nj < 4; ++nj)
                ldsm4t(bf[nj], bb + (lane & 15)*272 + (cn + nj*16 + (lane >> 4)*8)*2);
        }

        if (AMODE == 1){
            if (it + 1 < NIT){
                int ns = stg + 1; if (ns >= 3) ns -= 3;
                store_norm(ns * STAGE);
            }
            if (it + 2 < NIT){
                int ps = stg + 2; if (ps >= 3) ps -= 3;
                ra = *(const uint4*)(gA1 + (size_t)(it + 2) * 16);
                cpa16(sb + ps*STAGE + sBo, gB + (size_t)(it + 2) * 16 * (size_t)KS);
                asm volatile("cp.async.commit_group;");
            }
        } else {
            if (it + 2 < NIT){
                int ps = stg + 2; if (ps >= 3) ps -= 3;
                uint32_t base = sb + ps * STAGE;
                size_t ka = (size_t)(it + 2) * 16;
                #pragma unroll
                for (int i = 0; i < 2; ++i) cpa16(base + sAo[i], gA[i] + ka);
                cpa16(base + sBo, gB + ka * (size_t)KS);
                asm volatile("cp.async.commit_group;");
            }
        }

        #pragma unroll
        for (int mi = 0; mi < 2; ++mi){
            #pragma unroll
            for (int nj = 0; nj < 4; ++nj){
                #pragma unroll
                for (int blk = 0; blk < 2; ++blk){
                    float* d = acc[mi][nj*2 + blk];
                    mma16816(d, af[0][mi], &bf[nj][blk*2]);
                    mma16816(d, af[1][mi], &bf[nj][blk*2]);
                }
            }
        }
        if (++stg == 3) stg = 0;
    }

    const int gr = lane >> 2, tc = lane & 3;

    if (EPI == 3){
        float s = 0.f, s2 = 0.f;
        #pragma unroll
        for (int mi = 0; mi < 2; ++mi)
            #pragma unroll
            for (int n8 = 0; n8 < 8; ++n8)
                #pragma unroll
                for (int e = 0; e < 4; ++e){
                    float v = acc[mi][n8][e];
                    s += v; s2 += v*v;
                }
        #pragma unroll
        for (int o = 16; o; o >>= 1){
            s  += __shfl_xor_sync(0xffffffffu, s,  o);
            s2 += __shfl_xor_sync(0xffffffffu, s2, o);
        }
        if (lane == 0){
            int bi = (z >> 3) * 128 + (n0 >> 6) + (cn >> 6);
            atomicAdd(&sums[bi*2],   s);
            atomicAdd(&sums[bi*2+1], s2);
        }
    }

    #pragma unroll
    for (int mi = 0; mi < 2; ++mi){
        int r0 = m0 + rm + mi*16 + gr;
        #pragma unroll
        for (int n8 = 0; n8 < 8; ++n8){
            float* d = acc[mi][n8];
            int col = n0 + cn + n8*8 + tc*2;
            if (EPI == 0){
                __half* Ch = (__half*)C0;
                size_t zc = (size_t)z * (size_t)Cz;
                size_t o0 = zc + (size_t)r0*ldc + col;
                size_t o1 = zc + (size_t)(r0+8)*ldc + col;
                *(__half2*)(Ch + o0) = __halves2half2(__float2half_rn(d[0]), __float2half_rn(d[1]));
                *(__half2*)(Ch + o1) = __halves2half2(__float2half_rn(d[2]), __float2half_rn(d[3]));
            } else if (EPI == 1){
                __half* Ch = (__half*)C0;
                __half* Cl = (__half*)C1;
                size_t zc = (size_t)z * (size_t)Cz;
                float v0 = gelu_exact(d[0]*iscale)*oscale;
                float v1 = gelu_exact(d[1]*iscale)*oscale;
                float v2 = gelu_exact(d[2]*iscale)*oscale;
                float v3 = gelu_exact(d[3]*iscale)*oscale;
                __half h0,l0,h1,l1,h2,l2,h3,l3;
                split16(v0,h0,l0); split16(v1,h1,l1);
                split16(v2,h2,l2); split16(v3,h3,l3);
                size_t o0 = zc + (size_t)r0*ldc + col;
                size_t o1 = zc + (size_t)(r0+8)*ldc + col;
                *(__half2*)(Ch + o0) = __halves2half2(h0, h1);
                *(__half2*)(Cl + o0) = __halves2half2(l0, l1);
                *(__half2*)(Ch + o1) = __halves2half2(h2, h3);
                *(__half2*)(Cl + o1) = __halves2half2(l2, l3);
            } else if (EPI == 2){
                float* Cf = (float*)C0;
                size_t zc = (size_t)z * (size_t)Cz;
                float2 w0; w0.x = d[0]*oscale; w0.y = d[1]*oscale;
                float2 w1; w1.x = d[2]*oscale; w1.y = d[3]*oscale;
                *(float2*)(Cf + zc + (size_t)r0*ldc + col) = w0;
                *(float2*)(Cf + zc + (size_t)(r0+8)*ldc + col) = w1;
            } else {
                __half* Ch = (__half*)C0;
                size_t zb = (size_t)(z >> 3) * 8388608ull + (size_t)(z & 7) * 64ull;
                size_t o = zb + (size_t)(col >> 6)*65536 + (col & 63);
                *(__half2*)(Ch + o + (size_t)r0*512)
                    = __halves2half2(__float2half_rn(d[0]), __float2half_rn(d[1]));
                *(__half2*)(Ch + o + (size_t)(r0+8)*512)
                    = __halves2half2(__float2half_rn(d[2]), __float2half_rn(d[3]));
            }
        }
    }
}

// ------------------------------------------------------------------
// elementwise kernels
// ------------------------------------------------------------------
__global__ void ln_kernel(const float* __restrict__ u, const float* __restrict__ g,
                          const float* __restrict__ b,
                          __half* __restrict__ oh, __half* __restrict__ ol){
    int w = threadIdx.x >> 5, lane = threadIdx.x & 31;
    size_t row = (size_t)blockIdx.x * 8 + w;
    float4 v = *((const float4*)(u + row*128) + lane);
    float s = v.x + v.y + v.z + v.w;
    #pragma unroll
    for(int o=16;o;o>>=1) s += __shfl_xor_sync(0xffffffffu, s, o);
    float m = s * (1.0f/128.0f);
    float d0=v.x-m, d1=v.y-m, d2=v.z-m, d3=v.w-m;
    float q = d0*d0 + d1*d1 + d2*d2 + d3*d3;
    #pragma unroll
    for(int o=16;o;o>>=1) q += __shfl_xor_sync(0xffffffffu, q, o);
    float inv = rsqrtf(q * (1.0f/128.0f) + EPSF);
    float4 gg = *((const float4*)g + lane);
    float4 bb = *((const float4*)b + lane);
    float r0 = d0*inv*gg.x + bb.x;
    float r1 = d1*inv*gg.y + bb.y;
    float r2 = d2*inv*gg.z + bb.z;
    float r3 = d3*inv*gg.w + bb.w;
    __half h0,l0,h1,l1,h2,l2,h3,l3;
    split16(r0,h0,l0); split16(r1,h1,l1); split16(r2,h2,l2); split16(r3,h3,l3);
    uint2 H; H.x = packh(h0,h1); H.y = packh(h2,h3);
    uint2 L; L.x = packh(l0,l1); L.y = packh(l2,l3);
    *(uint2*)(oh + row*128 + lane*4) = H;
    *(uint2*)(ol + row*128 + lane*4) = L;
}

// means read hi plane only
__global__ void mean_y_kernel(const __half* __restrict__ uh, float* __restrict__ mx){
    int bx = blockIdx.x; int d = threadIdx.x;
    size_t base = (size_t)bx*16384 + d;
    float s = 0.f;
    #pragma unroll 8
    for(int y=0;y<128;y++) s += __half2float(uh[base + (size_t)y*128]);
    mx[(size_t)bx*128 + d] = s * (1.0f/128.0f);
}
__global__ void mean_x_kernel(const __half* __restrict__ uh, float* __restrict__ my){
    int b = blockIdx.x >> 7, y = blockIdx.x & 127; int d = threadIdx.x;
    size_t base = (size_t)b*2097152 + (size_t)y*128 + d;
    float s = 0.f;
    #pragma unroll 8
    for(int x=0;x<128;x++) s += __half2float(uh[base + (size_t)x*16384]);
    my[(size_t)blockIdx.x*128 + d] = s * (1.0f/128.0f);
}

// pooling reducer v5: 1 row/block, 512 blocks, 512 threads, deep split-k
__global__ void __launch_bounds__(512) pool_kernel(const float* __restrict__ mrow,
    const float* __restrict__ Win,  const float* __restrict__ pWin,
    const float* __restrict__ lg,   const float* __restrict__ lb,
    const float* __restrict__ W1,   const float* __restrict__ b1,
    const float* __restrict__ W2,   const float* __restrict__ b2,
    float* __restrict__ out)
{
    __shared__ float row[128], part[512], s2[128], h1[256], gt[128];
    int t = threadIdx.x;
    int R0 = blockIdx.x;
    if (t < 128) row[t] = mrow[(size_t)R0*128 + t];
    __syncthreads();
    {
        int c = t & 127, kh = (t >> 7) * 32;
        float a0=0,a1=0;
        #pragma unroll 8
        for (int k = 0; k < 16; ++k){
            a0 += row[kh+k]    * Win[(kh+k)*128 + c];
            a1 += row[kh+k+16] * Win[(kh+k+16)*128 + c];
        }
        part[t] = a0+a1;
    }
    __syncthreads();
    if (t < 128) row[t] = (part[t] + part[t+128]) + (part[t+256] + part[t+384]);
    __syncthreads();
    {
        int c = t & 127, kh = (t >> 7) * 32;
        float a0=0,a1=0;
        #pragma unroll 8
        for (int k = 0; k < 16; ++k){
            a0 += row[kh+k]    * pWin[(kh+k)*128 + c];
            a1 += row[kh+k+16] * pWin[(kh+k+16)*128 + c];
        }
        part[t] = a0+a1;
    }
    __syncthreads();
    if (t < 128) s2[t] = (part[t] + part[t+128]) + (part[t+256] + part[t+384]);
    __syncthreads();
    if (t < 32){
        float x0 = s2[t], x1 = s2[t+32], x2 = s2[t+64], x3 = s2[t+96];
        float s = x0+x1+x2+x3;
        float q = x0*x0+x1*x1+x2*x2+x3*x3;
        #pragma unroll
        for(int o=16;o;o>>=1){ s += __shfl_xor_sync(0xffffffffu,s,o); q += __shfl_xor_sync(0xffffffffu,q,o); }
        float m = s * (1.0f/128.0f);
        float var = q * (1.0f/128.0f) - m*m;
        float inv = rsqrtf(var + EPSF);
        s2[t]    = (x0-m)*inv*lg[t]    + lb[t];
        s2[t+32] = (x1-m)*inv*lg[t+32] + lb[t+32];
        s2[t+64] = (x2-m)*inv*lg[t+64] + lb[t+64];
        s2[t+96] = (x3-m)*inv*lg[t+96] + lb[t+96];
    }
    __syncthreads();
    {
        int c = t & 255, kh = (t >> 8) * 64;
        float a0=0,a1=0,a2=0,a3=0;
        #pragma unroll 8
        for (int k = 0; k < 16; ++k){
            a0 += s2[kh+k]    * W1[(kh+k)*256 + c];
            a1 += s2[kh+k+16] * W1[(kh+k+16)*256 + c];
            a2 += s2[kh+k+32] * W1[(kh+k+32)*256 + c];
            a3 += s2[kh+k+48] * W1[(kh+k+48)*256 + c];
        }
        part[t] = (a0+a1)+(a2+a3);
    }
    __syncthreads();
    if (t < 256) h1[t] = b1[t] + part[t] + part[t+256];
    __syncthreads();
    if (t < 128) gt[t] = gelu_exact(h1[t]) * h1[128 + t];
    __syncthreads();
    {
        int c = t & 63, kh = (t >> 6) * 16;
        float a0=0,a1=0;
        #pragma unroll 8
        for (int k = 0; k < 8; ++k){
            a0 += gt[kh+k]   * W2[(kh+k)*64 + c];
            a1 += gt[kh+k+8] * W2[(kh+k+8)*64 + c];
        }
        part[t] = a0+a1;
    }
    __syncthreads();
    if (t < 64){
        float s = b2[t];
        #pragma unroll
        for (int j = 0; j < 8; ++j) s += part[t + 64*j];
        out[(size_t)R0*64 + t] = s;
    }
}

// qk projection + rotary (unchanged)
__global__ void qkrot_kernel(const float* __restrict__ uu,
    const float* __restrict__ Wqk, const float* __restrict__ pos,
    float* __restrict__ qo, float* __restrict__ ko)
{
    __shared__ float r[8][64];
    __shared__ float invf[96];
    __shared__ float pp[8];
    __shared__ float qs[8][192], ks[8][192];
    int t = threadIdx.x;
    int rb = blockIdx.x >> 3, h = blockIdx.x & 7;
    int R0 = rb * 8;
    int b = R0 >> 7;
    {
        int row = t >> 6, k = t & 63;
        r[row][k]   = uu[(size_t)(R0 + row)*64 + k];
        r[row+4][k] = uu[(size_t)(R0 + row + 4)*64 + k];
    }
    if (t < 96) invf[t] = powf(10000.0f, -(float)t*(1.0f/96.0f));
    if (t < 8)  pp[t] = pos[(R0 + t) & 127] * 64.0f;
    __syncthreads();
    for (int col = t; col < 384; col += 256){
        int which = col >= 192;
        int c = col - which*192;
        const float* w = Wqk + (size_t)which*1536 + h*192 + c;
        float a0=0,a1=0,a2=0,a3=0,a4=0,a5=0,a6=0,a7=0;
        #pragma unroll 8
        for (int k = 0; k < 64; ++k){
            float wv = w[(size_t)k*3072];
            a0 += r[0][k]*wv; a1 += r[1][k]*wv; a2 += r[2][k]*wv; a3 += r[3][k]*wv;
            a4 += r[4][k]*wv; a5 += r[5][k]*wv; a6 += r[6][k]*wv; a7 += r[7][k]*wv;
        }
        float* dst = which ? &ks[0][0] : &qs[0][0];
        dst[0*192+c]=a0; dst[1*192+c]=a1; dst[2*192+c]=a2; dst[3*192+c]=a3;
        dst[4*192+c]=a4; dst[5*192+c]=a5; dst[6*192+c]=a6; dst[7*192+c]=a7;
    }
    __syncthreads();
    for (int i = t; i < 1536; i += 256){
        int row = i / 192, c = i - row*192;
        int j = (c < 96) ? c : c - 96;
        float f = pp[row] * invf[j];
        float cs = cosf(f), sn = sinf(f);
        float q2, k2;
        if (c < 96){
            q2 = qs[row][c]*cs - qs[row][c+96]*sn;
            k2 = ks[row][c]*cs - ks[row][c+96]*sn;
        } else {
            q2 = qs[row][c]*cs + qs[row][c-96]*sn;
            k2 = ks[row][c]*cs + ks[row][c-96]*sn;
        }
        int n = (R0 + row) & 127;
        size_t idx = ((size_t)(b*8 + h)*128 + n)*192 + c;
        qo[idx] = q2; ko[idx] = k2;
    }
}

__global__ void quant3_kernel(const float* __restrict__ Wv, const float* __restrict__ Wo1,
                              const float* __restrict__ Wo2,
                              __half* __restrict__ wvh, __half* __restrict__ wo1h,
                              __half* __restrict__ wo2h){
    int i = blockIdx.x*256 + threadIdx.x;
    if (i < 65536)       wvh[i]          = __float2half_rn(Wv[i]);
    else if (i < 131072) wo1h[i-65536]   = __float2half_rn(Wo1[i-65536]);
    else if (i < 147456) wo2h[i-131072]  = __float2half_rn(Wo2[i-131072]);
}

// ---------------- fp32 sgemm for kx/ky (K=192, TRANSB), split epilogue ----------------
__global__ void __launch_bounds__(256) sgemm_tb_kernel(
    const float* __restrict__ Ag, const float* __restrict__ Bg,
    __half* __restrict__ Ch, __half* __restrict__ Cl,
    int K, int lda, int ldb, int ldc,
    long long bsA, long long bsB, long long bsC, float scale)
{
    const int z = blockIdx.z;
    const float* A = Ag + (size_t)z * (size_t)bsA;
    const float* B = Bg + (size_t)z * (size_t)bsB;
    const int m0 = blockIdx.y*64, n0 = blockIdx.x*64;
    const int tid = threadIdx.x;
    const int tx = tid & 15, ty = tid >> 4;
    __shared__ float As[16][64];
    __shared__ float Bs[16][64];
    float acc[4][4];
    #pragma unroll
    for(int i=0;i<4;i++)
        #pragma unroll
        for(int j=0;j<4;j++) acc[i][j]=0.f;
    const int arow = tid>>2, ac4 = (tid&3)*4;
    const int tcol = tid>>2, tr4 = (tid&3)*4;
    for(int k0=0;k0<K;k0+=16){
        float4 av = *(const float4*)(A + (size_t)(m0+arow)*lda + (k0+ac4));
        As[ac4+0][arow]=av.x; As[ac4+1][arow]=av.y; As[ac4+2][arow]=av.z; As[ac4+3][arow]=av.w;
        float4 bv = *(const float4*)(B + (size_t)(n0+tcol)*ldb + (k0+tr4));
        Bs[tr4+0][tcol]=bv.x; Bs[tr4+1][tcol]=bv.y; Bs[tr4+2][tcol]=bv.z; Bs[tr4+3][tcol]=bv.w;
        __syncthreads();
        #pragma unroll
        for(int k=0;k<16;k++){
            float4 a4 = *(const float4*)(&As[k][ty*4]);
            float4 b4 = *(const float4*)(&Bs[k][tx*4]);
            float a[4]={a4.x,a4.y,a4.z,a4.w};
            float bb[4]={b4.x,b4.y,b4.z,b4.w};
            #pragma unroll
            for(int i=0;i<4;i++)
                #pragma unroll
                for(int j=0;j<4;j++) acc[i][j] += a[i]*bb[j];
        }
        __syncthreads();
    }
    size_t zc = (size_t)z * (size_t)bsC;
    #pragma unroll
    for(int i=0;i<4;i++){
        int row = m0 + ty*4 + i;
        #pragma unroll
        for(int j=0;j<4;j+=2){
            int col = n0 + tx*4 + j;
            __half h0,l0,h1,l1;
            split16(acc[i][j]*scale,   h0, l0);
            split16(acc[i][j+1]*scale, h1, l1);
            size_t o = zc + (size_t)row*ldc + col;
            *(__half2*)(Ch + o) = __halves2half2(h0,h1);
            *(__half2*)(Cl + o) = __halves2half2(l0,l1);
        }
    }
}

// ------------------------------------------------------------------
// launch — multi-stream DAG, full GEMM chain (R13 schedule)
// ------------------------------------------------------------------
extern "C" void kernel_launch(void* const* d_in, const int* in_sizes, int n_in,
                              void* d_out, int out_size){
    const float* u      = (const float*)d_in[0];
    const float* pos_x  = (const float*)d_in[1];
    const float* pos_y  = (const float*)d_in[2];
    const float* ln_g   = (const float*)d_in[3];
    const float* ln_b   = (const float*)d_in[4];
    const float* Wv     = (const float*)d_in[5];
    const float* Win    = (const float*)d_in[6];
    const float* px_Win = (const float*)d_in[7];
    const float* px_g   = (const float*)d_in[8];
    const float* px_b   = (const float*)d_in[9];
    const float* px_W1  = (const float*)d_in[10];
    const float* px_b1  = (const float*)d_in[11];
    const float* px_W2  = (const float*)d_in[12];
    const float* px_b2  = (const float*)d_in[13];
    const float* py_Win = (const float*)d_in[14];
    const float* py_g   = (const float*)d_in[15];
    const float* py_b   = (const float*)d_in[16];
    const float* py_W1  = (const float*)d_in[17];
    const float* py_b1  = (const float*)d_in[18];
    const float* py_W2  = (const float*)d_in[19];
    const float* py_b2  = (const float*)d_in[20];
    const float* Wqk_x  = (const float*)d_in[21];
    const float* Wqk_y  = (const float*)d_in[22];
    const float* Wo1    = (const float*)d_in[23];
    const float* Wo2    = (const float*)d_in[24];
    float* out = (float*)d_out;

    __half *unh,*unl,*vph,*t1h,*t2s,*goh,*gol;
    __half *wvh,*wo1h,*wo2h,*kxmh,*kxml,*kymh,*kyml;
    float *mx,*my,*ux,*uy,*qx,*kxv,*qy,*kyv,*sums;
    cudaGetSymbolAddress((void**)&unh, g_unh);  cudaGetSymbolAddress((void**)&unl, g_unl);
    cudaGetSymbolAddress((void**)&vph, g_vph);
    cudaGetSymbolAddress((void**)&t1h, g_t1h);
    cudaGetSymbolAddress((void**)&t2s, g_t2s);
    cudaGetSymbolAddress((void**)&goh, g_goh);  cudaGetSymbolAddress((void**)&gol, g_gol);
    cudaGetSymbolAddress((void**)&wvh, g_wvh);
    cudaGetSymbolAddress((void**)&wo1h,g_wo1h);
    cudaGetSymbolAddress((void**)&wo2h,g_wo2h);
    cudaGetSymbolAddress((void**)&kxmh,g_kxmh); cudaGetSymbolAddress((void**)&kxml,g_kxml);
    cudaGetSymbolAddress((void**)&kymh,g_kymh); cudaGetSymbolAddress((void**)&kyml,g_kyml);
    cudaGetSymbolAddress((void**)&mx,  g_mx);   cudaGetSymbolAddress((void**)&my,  g_my);
    cudaGetSymbolAddress((void**)&ux,  g_ux);   cudaGetSymbolAddress((void**)&uy,  g_uy);
    cudaGetSymbolAddress((void**)&qx,  g_qx);   cudaGetSymbolAddress((void**)&kxv, g_kxv);
    cudaGetSymbolAddress((void**)&qy,  g_qy);   cudaGetSymbolAddress((void**)&kyv, g_kyv);
    cudaGetSymbolAddress((void**)&sums, g_sums);

    cudaFuncSetAttribute(mma_kernel<0,0,0>, cudaFuncAttributeMaxDynamicSharedMemorySize, SMEMB);
    cudaFuncSetAttribute(mma_kernel<0,1,0>, cudaFuncAttributeMaxDynamicSharedMemorySize, SMEMB);
    cudaFuncSetAttribute(mma_kernel<0,0,3>, cudaFuncAttributeMaxDynamicSharedMemorySize, SMEMB);
    cudaFuncSetAttribute(mma_kernel<1,0,1>, cudaFuncAttributeMaxDynamicSharedMemorySize, SMEMB);
    cudaFuncSetAttribute(mma_kernel<0,0,2>, cudaFuncAttributeMaxDynamicSharedMemorySize, SMEMB);

    cudaStream_t sA = g_res.sA, sB = g_res.sB, sC = g_res.sC;

    // ---- fork ----
    cudaEventRecord(g_res.evF, 0);
    cudaStreamWaitEvent(sA, g_res.evF, 0);
    cudaStreamWaitEvent(sB, g_res.evF, 0);
    cudaStreamWaitEvent(sC, g_res.evF, 0);

    quant3_kernel<<<576,256,0,sC>>>(Wv, Wo1, Wo2, wvh, wo1h, wo2h);
    cudaEventRecord(g_res.evQ, sC);
    cudaMemsetAsync(sums, 0, 1024*sizeof(float), sB);

    // ---- main: ln ----
    ln_kernel<<<8192,256,0,0>>>(u, ln_g, ln_b, unh, unl);
    cudaEventRecord(g_res.evLn, 0);

    // ---- branch A (x-chain) on sA ----
    cudaStreamWaitEvent(sA, g_res.evLn, 0);
    mean_y_kernel<<<512,128,0,sA>>>(unh, mx);
    pool_kernel<<<512,512,0,sA>>>(mx, Win, px_Win, px_g, px_b, px_W1, px_b1, px_W2, px_b2, ux);
    qkrot_kernel<<<512,256,0,sA>>>(ux, Wqk_x, pos_x, qx, kxv);
    sgemm_tb_kernel<<<dim3(2,2,32),256,0,sA>>>(qx, kxv, kxmh, kxml, 192, 192, 192, 128,
                                               24576, 24576, 16384, S_K);
    cudaEventRecord(g_res.evX, sA);

    // ---- branch B (y-chain) on sB ----
    cudaStreamWaitEvent(sB, g_res.evLn, 0);
    mean_x_kernel<<<512,128,0,sB>>>(unh, my);
    pool_kernel<<<512,512,0,sB>>>(my, Win, py_Win, py_g, py_b, py_W1, py_b1, py_W2, py_b2, uy);
    qkrot_kernel<<<512,256,0,sB>>>(uy, Wqk_y, pos_y, qy, kyv);
    sgemm_tb_kernel<<<dim3(2,2,32),256,0,sB>>>(qy, kyv, kymh, kyml, 192, 192, 192, 128,
                                               24576, 24576, 16384, S_K);
    cudaEventRecord(g_res.evY, sB);

    // ---- main: full v-GEMM overlapping both branches ----
    cudaStreamWaitEvent(0, g_res.evQ, 0);
    mma_kernel<0,0,0><<<dim3(4,512,1),256,SMEMB,0>>>(unh, unl, wvh, vph, nullptr,
        nullptr, 128, 512, 64, 512, 0, 0, 0, 1.0f, 1.0f);

    // join x, attend-x
    cudaStreamWaitEvent(0, g_res.evX, 0);
    mma_kernel<0,1,0><<<dim3(64,1,32),256,SMEMB,0>>>(kxmh, kxml, vph, t1h, nullptr,
        nullptr, 128, 65536, 512, 8192, 16384, 0, 1048576, 1.0f, 1.0f);

    // join y, attend-y (+stats)
    cudaStreamWaitEvent(0, g_res.evY, 0);
    mma_kernel<0,0,3><<<dim3(64,1,32),256,SMEMB,0>>>(kymh, kyml, t1h, t2s, nullptr,
        sums, 128, 64, 8192, 0, 16384, 1048576, 0, 1.0f, 1.0f);
    // gelu GEMM with fused instance-norm (stats inline)
    mma_kernel<1,0,1><<<dim3(1,512,1),256,SMEMB,0>>>(t2s, nullptr, wo1h, goh, gol,
        sums, 512, 128, 64, 128, 0, 0, 0, S_GI, S_GO);
    // out = (go'@Wo2) * 2^-21
    mma_kernel<0,0,2><<<dim3(1,512,1),256,SMEMB,0>>>(goh, gol, wo2h, out, nullptr,
        nullptr, 128, 128, 64, 128, 0, 0, 0, 1.0f, S_OUT);
}

// round 17
// speedup vs baseline: 1.0496x; 1.0273x over previous
#include <cuda_runtime.h>
#include <cuda_fp16.h>
#include <stdint.h>

#define EPSF 1e-5f

#define S_K   65536.0f
#define S_IN  524288.0f
#define S_GI  (1.0f/524288.0f)
#define S_GO  2097152.0f
#define S_OUT (1.0f/2097152.0f)

static __device__ __forceinline__ float gelu_exact(float x){
    return 0.5f * x * (1.0f + erff(x * 0.70710678118654752440f));
}
static __device__ __forceinline__ void split16(float v, __half& h, __half& l){
    h = __float2half_rn(v);
    l = __float2half_rn(v - __half2float(h));
}
static __device__ __forceinline__ uint32_t packh(__half a, __half b){
    return (uint32_t)__half_as_ushort(a) | ((uint32_t)__half_as_ushort(b)<<16);
}

// ------------------------------------------------------------------
// static streams/events
// ------------------------------------------------------------------
struct GpuRes {
    cudaStream_t sA, sB, sC;
    cudaEvent_t evF, evLn, evQ, evQo, evX, evY;
    GpuRes(){
        cudaStreamCreateWithFlags(&sA, cudaStreamNonBlocking);
        cudaStreamCreateWithFlags(&sB, cudaStreamNonBlocking);
        cudaStreamCreateWithFlags(&sC, cudaStreamNonBlocking);
        cudaEventCreateWithFlags(&evF,  cudaEventDisableTiming);
        cudaEventCreateWithFlags(&evLn, cudaEventDisableTiming);
        cudaEventCreateWithFlags(&evQ,  cudaEventDisableTiming);
        cudaEventCreateWithFlags(&evQo, cudaEventDisableTiming);
        cudaEventCreateWithFlags(&evX,  cudaEventDisableTiming);
        cudaEventCreateWithFlags(&evY,  cudaEventDisableTiming);
    }
};
static GpuRes g_res;

// ------------------------------------------------------------------
// scratch (device globals)
// ------------------------------------------------------------------
__device__ __align__(16) __half g_unh [8388608];
__device__ __align__(16) __half g_unl [8388608];
__device__ __align__(16) __half g_vph [33554432];
__device__ __align__(16) __half g_t1h [33554432];
__device__ __align__(16) __half g_t2s [33554432];
__device__ __align__(16) __half g_goh [8388608];
__device__ __align__(16) __half g_gol [8388608];
__device__ __align__(16) __half g_wvh [65536];
__device__ __align__(16) __half g_wo1h[65536];
__device__ __align__(16) __half g_wo2h[16384];
__device__ __align__(16) float  g_sums [1024];
__device__ __align__(16) float g_mx [65536];
__device__ __align__(16) float g_my [65536];
__device__ __align__(16) float g_ux [32768];
__device__ __align__(16) float g_uy [32768];
__device__ __align__(16) float g_qx [786432];
__device__ __align__(16) float g_kxv[786432];
__device__ __align__(16) float g_qy [786432];
__device__ __align__(16) float g_kyv[786432];
__device__ __align__(16) __half g_kxmh[524288], g_kxml[524288];
__device__ __align__(16) __half g_kymh[524288], g_kyml[524288];

// ------------------------------------------------------------------
// PTX helpers
// ------------------------------------------------------------------
static __device__ __forceinline__ uint32_t s2u(const void* p){
    uint32_t a;
    asm("{ .reg .u64 t; cvta.to.shared.u64 t, %1; cvt.u32.u64 %0, t; }" : "=r"(a) : "l"(p));
    return a;
}
static __device__ __forceinline__ void cpa16(uint32_t s, const void* g){
    asm volatile("cp.async.cg.shared.global [%0], [%1], 16;" :: "r"(s), "l"(g));
}
static __device__ __forceinline__ void ldsm4(uint32_t* r, uint32_t addr){
    asm volatile("ldmatrix.sync.aligned.m8n8.x4.shared.b16 {%0,%1,%2,%3}, [%4];"
        : "=r"(r[0]),"=r"(r[1]),"=r"(r[2]),"=r"(r[3]) : "r"(addr));
}
static __device__ __forceinline__ void ldsm4t(uint32_t* r, uint32_t addr){
    asm volatile("ldmatrix.sync.aligned.m8n8.x4.trans.shared.b16 {%0,%1,%2,%3}, [%4];"
        : "=r"(r[0]),"=r"(r[1]),"=r"(r[2]),"=r"(r[3]) : "r"(addr));
}
static __device__ __forceinline__ void mma16816(float* c, const uint32_t* a, const uint32_t* b){
    asm volatile("mma.sync.aligned.m16n8k16.row.col.f32.f16.f16.f32 "
        "{%0,%1,%2,%3}, {%4,%5,%6,%7}, {%8,%9}, {%0,%1,%2,%3};"
        : "+f"(c[0]),"+f"(c[1]),"+f"(c[2]),"+f"(c[3])
        : "r"(a[0]),"r"(a[1]),"r"(a[2]),"r"(a[3]), "r"(b[0]),"r"(b[1]));
}

// ------------------------------------------------------------------
// fp16 split MMA GEMM, 3-stage pipeline.
// AMODE 0: A from two pre-split planes (2 MMAs/step).
// AMODE 1: A from one fp16 plane, normalized, split hi/lo (2 MMAs/step).
// AMODE 2: A from one fp16 plane, normalized, hi-only (1 MMA/step).
// ------------------------------------------------------------------
#define APB   6144
#define BPB   4352
#define STAGE (2*APB + BPB)
#define SMEMB (3*STAGE)

template<int AMODE, int BZMODE, int EPI>
__global__ void __launch_bounds__(256,2) mma_kernel(
    const __half* __restrict__ Ahi, const __half* __restrict__ Alo,
    const __half* __restrict__ Bhi,
    void* __restrict__ C0, void* __restrict__ C1,
    float* __restrict__ sums,
    int K, int KS, int NS, int ldc,
    long long Az, long long Bz, long long Cz,
    float iscale, float oscale)
{
    constexpr int APL = (AMODE == 2) ? 1 : 2;   // A planes in mainloop
    extern __shared__ __align__(16) char smem[];
    const uint32_t sb = s2u(smem);
    const int tid  = threadIdx.x;
    const int lane = tid & 31;
    const int wid  = tid >> 5;
    const int rm   = (wid >> 1) * 32;
    const int cn   = (wid & 1) * 64;
    const int z    = blockIdx.z;
    const int n0   = blockIdx.x * 128;
    const int m0   = blockIdx.y * 128;

    size_t zA = (size_t)z * (size_t)Az;
    size_t zB;
    if (BZMODE == 0) zB = (size_t)z * (size_t)Bz;
    else             zB = (size_t)(z >> 3) * 8388608ull + (size_t)(z & 7) * 64ull;

    const __half* gA[2]; uint32_t sAo[2];
    const __half* gA1 = nullptr;
    uint32_t sA1 = 0;
    float2 stv = make_float2(0.f, 1.f);
    uint4 ra;
    if (AMODE == 0){
        #pragma unroll
        for (int i = 0; i < 2; ++i){
            int c = tid + 256*i;
            int plane = c >> 8, row = (c >> 1) & 127, half = c & 1;
            gA[i] = (plane ? Alo : Ahi) + zA + (size_t)(m0 + row) * (size_t)K + half*8;
            sAo[i] = plane*APB + row*48 + half*16;
        }
    } else {
        float S  = sums[2*blockIdx.y];
        float S2 = sums[2*blockIdx.y + 1];
        float m  = S * (1.0f/65536.0f);
        float var_s = S2 * (1.0f/65536.0f) - m*m;
        stv = make_float2(m, rsqrtf(var_s * 0x1p-64f + EPSF) * (0x1p-32f * S_IN));
        int row = tid >> 1, half = tid & 1;
        gA1 = Ahi + zA + (size_t)(m0 + row) * (size_t)K + half*8;
        sA1 = row*48 + half*16;
    }
    const __half* gB; uint32_t sBo;
    {
        int row = tid >> 4, ch = tid & 15;
        gB = Bhi + zB + (size_t)row * (size_t)KS
           + (size_t)((n0 >> 6) + (ch >> 3)) * (size_t)NS + (ch & 7)*8;
        sBo = 2*APB + row*272 + ch*16;
    }

    const int NIT = K >> 4;

    auto store_norm = [&](int sbyte){
        const __half2* hp = (const __half2*)&ra;
        uint4 H, L;
        uint32_t* Hp = (uint32_t*)&H;
        uint32_t* Lp = (uint32_t*)&L;
        #pragma unroll
        for (int j = 0; j < 4; ++j){
            float2 f = __half22float2(hp[j]);
            float v0 = (f.x - stv.x) * stv.y;
            float v1 = (f.y - stv.x) * stv.y;
            if (APL == 2){
                __half h0,l0,h1,l1;
                split16(v0,h0,l0); split16(v1,h1,l1);
                Hp[j] = packh(h0,h1);
                Lp[j] = packh(l0,l1);
            } else {
                Hp[j] = packh(__float2half_rn(v0), __float2half_rn(v1));
            }
        }
        *(uint4*)(smem + sbyte + sA1) = H;
        if (APL == 2) *(uint4*)(smem + sbyte + APB + sA1) = L;
    };

    if (AMODE == 0){
        #pragma unroll
        for (int s = 0; s < 2; ++s){
            uint32_t base = sb + s*STAGE;
            size_t ka = (size_t)s * 16;
            #pragma unroll
            for (int i = 0; i < 2; ++i) cpa16(base + sAo[i], gA[i] + ka);
            cpa16(base + sBo, gB + ka * (size_t)KS);
            asm volatile("cp.async.commit_group;");
        }
    } else {
        ra = *(const uint4*)gA1;
        store_norm(0);
        ra = *(const uint4*)(gA1 + 16);
        cpa16(sb + sBo, gB);
        asm volatile("cp.async.commit_group;");
        cpa16(sb + STAGE + sBo, gB + 16 * (size_t)KS);
        asm volatile("cp.async.commit_group;");
    }

    float acc[2][8][4];
    #pragma unroll
    for (int a = 0; a < 2; ++a)
        #pragma unroll
        for (int b = 0; b < 8; ++b)
            #pragma unroll
            for (int c = 0; c < 4; ++c) acc[a][b][c] = 0.f;

    int stg = 0;
    for (int it = 0; it < NIT; ++it){
        if (it < NIT-1) asm volatile("cp.async.wait_group 1;" ::: "memory");
        else            asm volatile("cp.async.wait_group 0;" ::: "memory");
        __syncthreads();

        const uint32_t st = sb + stg * STAGE;
        uint32_t af[2][2][4];
        uint32_t bf[4][4];
        #pragma unroll
        for (int p = 0; p < APL; ++p){
            uint32_t ab = st + p*APB;
            #pragma unroll
            for (int mi = 0; mi < 2; ++mi)
                ldsm4(af[p][mi], ab + (rm + mi*16 + (lane & 15))*48 + (lane >> 4)*16);
        }
        {
            uint32_t bb = st + 2*APB;
            #pragma unroll
            for (int nj = 0; nj < 4; ++nj)
                ldsm4t(bf[nj], bb + (lane & 15)*272 + (cn + nj*16 + (lane >> 4)*8)*2);
        }

        if (AMODE != 0){
            if (it + 1 < NIT){
                int ns = stg + 1; if (ns >= 3) ns -= 3;
                store_norm(ns * STAGE);
            }
            if (it + 2 < NIT){
                int ps = stg + 2; if (ps >= 3) ps -= 3;
                ra = *(const uint4*)(gA1 + (size_t)(it + 2) * 16);
                cpa16(sb + ps*STAGE + sBo, gB + (size_t)(it + 2) * 16 * (size_t)KS);
                asm volatile("cp.async.commit_group;");
            }
        } else {
            if (it + 2 < NIT){
                int ps = stg + 2; if (ps >= 3) ps -= 3;
                uint32_t base = sb + ps * STAGE;
                size_t ka = (size_t)(it + 2) * 16;
                #pragma unroll
                for (int i = 0; i < 2; ++i) cpa16(base + sAo[i], gA[i] + ka);
                cpa16(base + sBo, gB + ka * (size_t)KS);
                asm volatile("cp.async.commit_group;");
            }
        }

        #pragma unroll
        for (int mi = 0; mi < 2; ++mi){
            #pragma unroll
            for (int nj = 0; nj < 4; ++nj){
                #pragma unroll
                for (int blk = 0; blk < 2; ++blk){
                    float* d = acc[mi][nj*2 + blk];
                    mma16816(d, af[0][mi], &bf[nj][blk*2]);
                    if (APL == 2) mma16816(d, af[1][mi], &bf[nj][blk*2]);
                }
            }
        }
        if (++stg == 3) stg = 0;
    }

    const int gr = lane >> 2, tc = lane & 3;

    if (EPI == 3){
        float s = 0.f, s2 = 0.f;
        #pragma unroll
        for (int mi = 0; mi < 2; ++mi)
            #pragma unroll
            for (int n8 = 0; n8 < 8; ++n8)
                #pragma unroll
                for (int e = 0; e < 4; ++e){
                    float v = acc[mi][n8][e];
                    s += v; s2 += v*v;
                }
        #pragma unroll
        for (int o = 16; o; o >>= 1){
            s  += __shfl_xor_sync(0xffffffffu, s,  o);
            s2 += __shfl_xor_sync(0xffffffffu, s2, o);
        }
        if (lane == 0){
            int bi = (z >> 3) * 128 + (n0 >> 6) + (cn >> 6);
            atomicAdd(&sums[bi*2],   s);
            atomicAdd(&sums[bi*2+1], s2);
        }
    }

    #pragma unroll
    for (int mi = 0; mi < 2; ++mi){
        int r0 = m0 + rm + mi*16 + gr;
        #pragma unroll
        for (int n8 = 0; n8 < 8; ++n8){
            float* d = acc[mi][n8];
            int col = n0 + cn + n8*8 + tc*2;
            if (EPI == 0){
                __half* Ch = (__half*)C0;
                size_t zc = (size_t)z * (size_t)Cz;
                size_t o0 = zc + (size_t)r0*ldc + col;
                size_t o1 = zc + (size_t)(r0+8)*ldc + col;
                *(__half2*)(Ch + o0) = __halves2half2(__float2half_rn(d[0]), __float2half_rn(d[1]));
                *(__half2*)(Ch + o1) = __halves2half2(__float2half_rn(d[2]), __float2half_rn(d[3]));
            } else if (EPI == 1){
                __half* Ch = (__half*)C0;
                __half* Cl = (__half*)C1;
                size_t zc = (size_t)z * (size_t)Cz;
                float v0 = gelu_exact(d[0]*iscale)*oscale;
                float v1 = gelu_exact(d[1]*iscale)*oscale;
                float v2 = gelu_exact(d[2]*iscale)*oscale;
                float v3 = gelu_exact(d[3]*iscale)*oscale;
                __half h0,l0,h1,l1,h2,l2,h3,l3;
                split16(v0,h0,l0); split16(v1,h1,l1);
                split16(v2,h2,l2); split16(v3,h3,l3);
                size_t o0 = zc + (size_t)r0*ldc + col;
                size_t o1 = zc + (size_t)(r0+8)*ldc + col;
                *(__half2*)(Ch + o0) = __halves2half2(h0, h1);
                *(__half2*)(Cl + o0) = __halves2half2(l0, l1);
                *(__half2*)(Ch + o1) = __halves2half2(h2, h3);
                *(__half2*)(Cl + o1) = __halves2half2(l2, l3);
            } else if (EPI == 2){
                float* Cf = (float*)C0;
                size_t zc = (size_t)z * (size_t)Cz;
                float2 w0; w0.x = d[0]*oscale; w0.y = d[1]*oscale;
                float2 w1; w1.x = d[2]*oscale; w1.y = d[3]*oscale;
                *(float2*)(Cf + zc + (size_t)r0*ldc + col) = w0;
                *(float2*)(Cf + zc + (size_t)(r0+8)*ldc + col) = w1;
            } else {
                __half* Ch = (__half*)C0;
                size_t zb = (size_t)(z >> 3) * 8388608ull + (size_t)(z & 7) * 64ull;
                size_t o = zb + (size_t)(col >> 6)*65536 + (col & 63);
                *(__half2*)(Ch + o + (size_t)r0*512)
                    = __halves2half2(__float2half_rn(d[0]), __float2half_rn(d[1]));
                *(__half2*)(Ch + o + (size_t)(r0+8)*512)
                    = __halves2half2(__float2half_rn(d[2]), __float2half_rn(d[3]));
            }
        }
    }
}

// ------------------------------------------------------------------
// elementwise kernels
// ------------------------------------------------------------------
__global__ void ln_kernel(const float* __restrict__ u, const float* __restrict__ g,
                          const float* __restrict__ b,
                          __half* __restrict__ oh, __half* __restrict__ ol){
    int w = threadIdx.x >> 5, lane = threadIdx.x & 31;
    size_t row = (size_t)blockIdx.x * 8 + w;
    float4 v = *((const float4*)(u + row*128) + lane);
    float s = v.x + v.y + v.z + v.w;
    #pragma unroll
    for(int o=16;o;o>>=1) s += __shfl_xor_sync(0xffffffffu, s, o);
    float m = s * (1.0f/128.0f);
    float d0=v.x-m, d1=v.y-m, d2=v.z-m, d3=v.w-m;
    float q = d0*d0 + d1*d1 + d2*d2 + d3*d3;
    #pragma unroll
    for(int o=16;o;o>>=1) q += __shfl_xor_sync(0xffffffffu, q, o);
    float inv = rsqrtf(q * (1.0f/128.0f) + EPSF);
    float4 gg = *((const float4*)g + lane);
    float4 bb = *((const float4*)b + lane);
    float r0 = d0*inv*gg.x + bb.x;
    float r1 = d1*inv*gg.y + bb.y;
    float r2 = d2*inv*gg.z + bb.z;
    float r3 = d3*inv*gg.w + bb.w;
    __half h0,l0,h1,l1,h2,l2,h3,l3;
    split16(r0,h0,l0); split16(r1,h1,l1); split16(r2,h2,l2); split16(r3,h3,l3);
    uint2 H; H.x = packh(h0,h1); H.y = packh(h2,h3);
    uint2 L; L.x = packh(l0,l1); L.y = packh(l2,l3);
    *(uint2*)(oh + row*128 + lane*4) = H;
    *(uint2*)(ol + row*128 + lane*4) = L;
}

// means read BOTH planes
__global__ void mean_y_kernel(const __half* __restrict__ uh,
                              const __half* __restrict__ ul, float* __restrict__ mx){
    int bx = blockIdx.x; int d = threadIdx.x;
    size_t base = (size_t)bx*16384 + d;
    float s = 0.f;
    #pragma unroll 8
    for(int y=0;y<128;y++){
        size_t i = base + (size_t)y*128;
        s += __half2float(uh[i]) + __half2float(ul[i]);
    }
    mx[(size_t)bx*128 + d] = s * (1.0f/128.0f);
}
__global__ void mean_x_kernel(const __half* __restrict__ uh,
                              const __half* __restrict__ ul, float* __restrict__ my){
    int b = blockIdx.x >> 7, y = blockIdx.x & 127; int d = threadIdx.x;
    size_t base = (size_t)b*2097152 + (size_t)y*128 + d;
    float s = 0.f;
    #pragma unroll 8
    for(int x=0;x<128;x++){
        size_t i = base + (size_t)x*16384;
        s += __half2float(uh[i]) + __half2float(ul[i]);
    }
    my[(size_t)blockIdx.x*128 + d] = s * (1.0f/128.0f);
}

// pooling reducer v5 (unchanged)
__global__ void __launch_bounds__(512) pool_kernel(const float* __restrict__ mrow,
    const float* __restrict__ Win,  const float* __restrict__ pWin,
    const float* __restrict__ lg,   const float* __restrict__ lb,
    const float* __restrict__ W1,   const float* __restrict__ b1,
    const float* __restrict__ W2,   const float* __restrict__ b2,
    float* __restrict__ out)
{
    __shared__ float row[128], part[512], s2[128], h1[256], gt[128];
    int t = threadIdx.x;
    int R0 = blockIdx.x;
    if (t < 128) row[t] = mrow[(size_t)R0*128 + t];
    __syncthreads();
    {
        int c = t & 127, kh = (t >> 7) * 32;
        float a0=0,a1=0;
        #pragma unroll 8
        for (int k = 0; k < 16; ++k){
            a0 += row[kh+k]    * Win[(kh+k)*128 + c];
            a1 += row[kh+k+16] * Win[(kh+k+16)*128 + c];
        }
        part[t] = a0+a1;
    }
    __syncthreads();
    if (t < 128) row[t] = (part[t] + part[t+128]) + (part[t+256] + part[t+384]);
    __syncthreads();
    {
        int c = t & 127, kh = (t >> 7) * 32;
        float a0=0,a1=0;
        #pragma unroll 8
        for (int k = 0; k < 16; ++k){
            a0 += row[kh+k]    * pWin[(kh+k)*128 + c];
            a1 += row[kh+k+16] * pWin[(kh+k+16)*128 + c];
        }
        part[t] = a0+a1;
    }
    __syncthreads();
    if (t < 128) s2[t] = (part[t] + part[t+128]) + (part[t+256] + part[t+384]);
    __syncthreads();
    if (t < 32){
        float x0 = s2[t], x1 = s2[t+32], x2 = s2[t+64], x3 = s2[t+96];
        float s = x0+x1+x2+x3;
        float q = x0*x0+x1*x1+x2*x2+x3*x3;
        #pragma unroll
        for(int o=16;o;o>>=1){ s += __shfl_xor_sync(0xffffffffu,s,o); q += __shfl_xor_sync(0xffffffffu,q,o); }
        float m = s * (1.0f/128.0f);
        float var = q * (1.0f/128.0f) - m*m;
        float inv = rsqrtf(var + EPSF);
        s2[t]    = (x0-m)*inv*lg[t]    + lb[t];
        s2[t+32] = (x1-m)*inv*lg[t+32] + lb[t+32];
        s2[t+64] = (x2-m)*inv*lg[t+64] + lb[t+64];
        s2[t+96] = (x3-m)*inv*lg[t+96] + lb[t+96];
    }
    __syncthreads();
    {
        int c = t & 255, kh = (t >> 8) * 64;
        float a0=0,a1=0,a2=0,a3=0;
        #pragma unroll 8
        for (int k = 0; k < 16; ++k){
            a0 += s2[kh+k]    * W1[(kh+k)*256 + c];
            a1 += s2[kh+k+16] * W1[(kh+k+16)*256 + c];
            a2 += s2[kh+k+32] * W1[(kh+k+32)*256 + c];
            a3 += s2[kh+k+48] * W1[(kh+k+48)*256 + c];
        }
        part[t] = (a0+a1)+(a2+a3);
    }
    __syncthreads();
    if (t < 256) h1[t] = b1[t] + part[t] + part[t+256];
    __syncthreads();
    if (t < 128) gt[t] = gelu_exact(h1[t]) * h1[128 + t];
    __syncthreads();
    {
        int c = t & 63, kh = (t >> 6) * 16;
        float a0=0,a1=0;
        #pragma unroll 8
        for (int k = 0; k < 8; ++k){
            a0 += gt[kh+k]   * W2[(kh+k)*64 + c];
            a1 += gt[kh+k+8] * W2[(kh+k+8)*64 + c];
        }
        part[t] = a0+a1;
    }
    __syncthreads();
    if (t < 64){
        float s = b2[t];
        #pragma unroll
        for (int j = 0; j < 8; ++j) s += part[t + 64*j];
        out[(size_t)R0*64 + t] = s;
    }
}

// qk projection + rotary (unchanged)
__global__ void qkrot_kernel(const float* __restrict__ uu,
    const float* __restrict__ Wqk, const float* __restrict__ pos,
    float* __restrict__ qo, float* __restrict__ ko)
{
    __shared__ float r[8][64];
    __shared__ float invf[96];
    __shared__ float pp[8];
    __shared__ float qs[8][192], ks[8][192];
    int t = threadIdx.x;
    int rb = blockIdx.x >> 3, h = blockIdx.x & 7;
    int R0 = rb * 8;
    int b = R0 >> 7;
    {
        int row = t >> 6, k = t & 63;
        r[row][k]   = uu[(size_t)(R0 + row)*64 + k];
        r[row+4][k] = uu[(size_t)(R0 + row + 4)*64 + k];
    }
    if (t < 96) invf[t] = powf(10000.0f, -(float)t*(1.0f/96.0f));
    if (t < 8)  pp[t] = pos[(R0 + t) & 127] * 64.0f;
    __syncthreads();
    for (int col = t; col < 384; col += 256){
        int which = col >= 192;
        int c = col - which*192;
        const float* w = Wqk + (size_t)which*1536 + h*192 + c;
        float a0=0,a1=0,a2=0,a3=0,a4=0,a5=0,a6=0,a7=0;
        #pragma unroll 8
        for (int k = 0; k < 64; ++k){
            float wv = w[(size_t)k*3072];
            a0 += r[0][k]*wv; a1 += r[1][k]*wv; a2 += r[2][k]*wv; a3 += r[3][k]*wv;
            a4 += r[4][k]*wv; a5 += r[5][k]*wv; a6 += r[6][k]*wv; a7 += r[7][k]*wv;
        }
        float* dst = which ? &ks[0][0] : &qs[0][0];
        dst[0*192+c]=a0; dst[1*192+c]=a1; dst[2*192+c]=a2; dst[3*192+c]=a3;
        dst[4*192+c]=a4; dst[5*192+c]=a5; dst[6*192+c]=a6; dst[7*192+c]=a7;
    }
    __syncthreads();
    for (int i = t; i < 1536; i += 256){
        int row = i / 192, c = i - row*192;
        int j = (c < 96) ? c : c - 96;
        float f = pp[row] * invf[j];
        float cs = cosf(f), sn = sinf(f);
        float q2, k2;
        if (c < 96){
            q2 = qs[row][c]*cs - qs[row][c+96]*sn;
            k2 = ks[row][c]*cs - ks[row][c+96]*sn;
        } else {
            q2 = qs[row][c]*cs + qs[row][c-96]*sn;
            k2 = ks[row][c]*cs + ks[row][c-96]*sn;
        }
        int n = (R0 + row) & 127;
        size_t idx = ((size_t)(b*8 + h)*128 + n)*192 + c;
        qo[idx] = q2; ko[idx] = k2;
    }
}

__global__ void quantWv_kernel(const float* __restrict__ Wv, __half* __restrict__ wvh){
    int i = blockIdx.x*256 + threadIdx.x;
    wvh[i] = __float2half_rn(Wv[i]);
}
__global__ void quantWo_kernel(const float* __restrict__ Wo1, const float* __restrict__ Wo2,
                               __half* __restrict__ wo1h, __half* __restrict__ wo2h){
    int i = blockIdx.x*256 + threadIdx.x;
    if (i < 65536)      wo1h[i]        = __float2half_rn(Wo1[i]);
    else if (i < 81920) wo2h[i-65536]  = __float2half_rn(Wo2[i-65536]);
}

// ---------------- fp32 sgemm for kx/ky (K=192, TRANSB), split epilogue ----------------
__global__ void __launch_bounds__(256) sgemm_tb_kernel(
    const float* __restrict__ Ag, const float* __restrict__ Bg,
    __half* __restrict__ Ch, __half* __restrict__ Cl,
    int K, int lda, int ldb, int ldc,
    long long bsA, long long bsB, long long bsC, float scale)
{
    const int z = blockIdx.z;
    const float* A = Ag + (size_t)z * (size_t)bsA;
    const float* B = Bg + (size_t)z * (size_t)bsB;
    const int m0 = blockIdx.y*64, n0 = blockIdx.x*64;
    const int tid = threadIdx.x;
    const int tx = tid & 15, ty = tid >> 4;
    __shared__ float As[16][64];
    __shared__ float Bs[16][64];
    float acc[4][4];
    #pragma unroll
    for(int i=0;i<4;i++)
        #pragma unroll
        for(int j=0;j<4;j++) acc[i][j]=0.f;
    const int arow = tid>>2, ac4 = (tid&3)*4;
    const int tcol = tid>>2, tr4 = (tid&3)*4;
    for(int k0=0;k0<K;k0+=16){
        float4 av = *(const float4*)(A + (size_t)(m0+arow)*lda + (k0+ac4));
        As[ac4+0][arow]=av.x; As[ac4+1][arow]=av.y; As[ac4+2][arow]=av.z; As[ac4+3][arow]=av.w;
        float4 bv = *(const float4*)(B + (size_t)(n0+tcol)*ldb + (k0+tr4));
        Bs[tr4+0][tcol]=bv.x; Bs[tr4+1][tcol]=bv.y; Bs[tr4+2][tcol]=bv.z; Bs[tr4+3][tcol]=bv.w;
        __syncthreads();
        #pragma unroll
        for(int k=0;k<16;k++){
            float4 a4 = *(const float4*)(&As[k][ty*4]);
            float4 b4 = *(const float4*)(&Bs[k][tx*4]);
            float a[4]={a4.x,a4.y,a4.z,a4.w};
            float bb[4]={b4.x,b4.y,b4.z,b4.w};
            #pragma unroll
            for(int i=0;i<4;i++)
                #pragma unroll
                for(int j=0;j<4;j++) acc[i][j] += a[i]*bb[j];
        }
        __syncthreads();
    }
    size_t zc = (size_t)z * (size_t)bsC;
    #pragma unroll
    for(int i=0;i<4;i++){
        int row = m0 + ty*4 + i;
        #pragma unroll
        for(int j=0;j<4;j+=2){
            int col = n0 + tx*4 + j;
            __half h0,l0,h1,l1;
            split16(acc[i][j]*scale,   h0, l0);
            split16(acc[i][j+1]*scale, h1, l1);
            size_t o = zc + (size_t)row*ldc + col;
            *(__half2*)(Ch + o) = __halves2half2(h0,h1);
            *(__half2*)(Cl + o) = __halves2half2(l0,l1);
        }
    }
}

// ------------------------------------------------------------------
// launch — multi-stream DAG, full GEMM chain (sC properly joined)
// ------------------------------------------------------------------
extern "C" void kernel_launch(void* const* d_in, const int* in_sizes, int n_in,
                              void* d_out, int out_size){
    const float* u      = (const float*)d_in[0];
    const float* pos_x  = (const float*)d_in[1];
    const float* pos_y  = (const float*)d_in[2];
    const float* ln_g   = (const float*)d_in[3];
    const float* ln_b   = (const float*)d_in[4];
    const float* Wv     = (const float*)d_in[5];
    const float* Win    = (const float*)d_in[6];
    const float* px_Win = (const float*)d_in[7];
    const float* px_g   = (const float*)d_in[8];
    const float* px_b   = (const float*)d_in[9];
    const float* px_W1  = (const float*)d_in[10];
    const float* px_b1  = (const float*)d_in[11];
    const float* px_W2  = (const float*)d_in[12];
    const float* px_b2  = (const float*)d_in[13];
    const float* py_Win = (const float*)d_in[14];
    const float* py_g   = (const float*)d_in[15];
    const float* py_b   = (const float*)d_in[16];
    const float* py_W1  = (const float*)d_in[17];
    const float* py_b1  = (const float*)d_in[18];
    const float* py_W2  = (const float*)d_in[19];
    const float* py_b2  = (const float*)d_in[20];
    const float* Wqk_x  = (const float*)d_in[21];
    const float* Wqk_y  = (const float*)d_in[22];
    const float* Wo1    = (const float*)d_in[23];
    const float* Wo2    = (const float*)d_in[24];
    float* out = (float*)d_out;

    __half *unh,*unl,*vph,*t1h,*t2s,*goh,*gol;
    __half *wvh,*wo1h,*wo2h,*kxmh,*kxml,*kymh,*kyml;
    float *mx,*my,*ux,*uy,*qx,*kxv,*qy,*kyv,*sums;
    cudaGetSymbolAddress((void**)&unh, g_unh);  cudaGetSymbolAddress((void**)&unl, g_unl);
    cudaGetSymbolAddress((void**)&vph, g_vph);
    cudaGetSymbolAddress((void**)&t1h, g_t1h);
    cudaGetSymbolAddress((void**)&t2s, g_t2s);
    cudaGetSymbolAddress((void**)&goh, g_goh);  cudaGetSymbolAddress((void**)&gol, g_gol);
    cudaGetSymbolAddress((void**)&wvh, g_wvh);
    cudaGetSymbolAddress((void**)&wo1h,g_wo1h);
    cudaGetSymbolAddress((void**)&wo2h,g_wo2h);
    cudaGetSymbolAddress((void**)&kxmh,g_kxmh); cudaGetSymbolAddress((void**)&kxml,g_kxml);
    cudaGetSymbolAddress((void**)&kymh,g_kymh); cudaGetSymbolAddress((void**)&kyml,g_kyml);
    cudaGetSymbolAddress((void**)&mx,  g_mx);   cudaGetSymbolAddress((void**)&my,  g_my);
    cudaGetSymbolAddress((void**)&ux,  g_ux);   cudaGetSymbolAddress((void**)&uy,  g_uy);
    cudaGetSymbolAddress((void**)&qx,  g_qx);   cudaGetSymbolAddress((void**)&kxv, g_kxv);
    cudaGetSymbolAddress((void**)&qy,  g_qy);   cudaGetSymbolAddress((void**)&kyv, g_kyv);
    cudaGetSymbolAddress((void**)&sums, g_sums);

    cudaFuncSetAttribute(mma_kernel<0,0,0>, cudaFuncAttributeMaxDynamicSharedMemorySize, SMEMB);
    cudaFuncSetAttribute(mma_kernel<0,1,0>, cudaFuncAttributeMaxDynamicSharedMemorySize, SMEMB);
    cudaFuncSetAttribute(mma_kernel<0,0,3>, cudaFuncAttributeMaxDynamicSharedMemorySize, SMEMB);
    cudaFuncSetAttribute(mma_kernel<2,0,1>, cudaFuncAttributeMaxDynamicSharedMemorySize, SMEMB);
    cudaFuncSetAttribute(mma_kernel<0,0,2>, cudaFuncAttributeMaxDynamicSharedMemorySize, SMEMB);

    cudaStream_t sA = g_res.sA, sB = g_res.sB, sC = g_res.sC;

    // ---- fork ----
    cudaEventRecord(g_res.evF, 0);
    cudaStreamWaitEvent(sA, g_res.evF, 0);
    cudaStreamWaitEvent(sB, g_res.evF, 0);
    cudaStreamWaitEvent(sC, g_res.evF, 0);

    // Wv quant first (gates v-GEMM); Wo quant after; evQo joins sC back.
    quantWv_kernel<<<256,256,0,sC>>>(Wv, wvh);
    cudaEventRecord(g_res.evQ, sC);
    quantWo_kernel<<<320,256,0,sC>>>(Wo1, Wo2, wo1h, wo2h);
    cudaEventRecord(g_res.evQo, sC);
    cudaMemsetAsync(sums, 0, 1024*sizeof(float), sB);

    // ---- main: ln ----
    ln_kernel<<<8192,256,0,0>>>(u, ln_g, ln_b, unh, unl);
    cudaEventRecord(g_res.evLn, 0);

    // ---- branch A (x-chain) on sA ----
    cudaStreamWaitEvent(sA, g_res.evLn, 0);
    mean_y_kernel<<<512,128,0,sA>>>(unh, unl, mx);
    pool_kernel<<<512,512,0,sA>>>(mx, Win, px_Win, px_g, px_b, px_W1, px_b1, px_W2, px_b2, ux);
    qkrot_kernel<<<512,256,0,sA>>>(ux, Wqk_x, pos_x, qx, kxv);
    sgemm_tb_kernel<<<dim3(2,2,32),256,0,sA>>>(qx, kxv, kxmh, kxml, 192, 192, 192, 128,
                                               24576, 24576, 16384, S_K);
    cudaEventRecord(g_res.evX, sA);

    // ---- branch B (y-chain) on sB ----
    cudaStreamWaitEvent(sB, g_res.evLn, 0);
    mean_x_kernel<<<512,128,0,sB>>>(unh, unl, my);
    pool_kernel<<<512,512,0,sB>>>(my, Win, py_Win, py_g, py_b, py_W1, py_b1, py_W2, py_b2, uy);
    qkrot_kernel<<<512,256,0,sB>>>(uy, Wqk_y, pos_y, qy, kyv);
    sgemm_tb_kernel<<<dim3(2,2,32),256,0,sB>>>(qy, kyv, kymh, kyml, 192, 192, 192, 128,
                                               24576, 24576, 16384, S_K);
    cudaEventRecord(g_res.evY, sB);

    // ---- main: full v-GEMM overlapping both branches ----
    cudaStreamWaitEvent(0, g_res.evQ, 0);
    mma_kernel<0,0,0><<<dim3(4,512,1),256,SMEMB,0>>>(unh, unl, wvh, vph, nullptr,
        nullptr, 128, 512, 64, 512, 0, 0, 0, 1.0f, 1.0f);

    // join x, attend-x
    cudaStreamWaitEvent(0, g_res.evX, 0);
    mma_kernel<0,1,0><<<dim3(64,1,32),256,SMEMB,0>>>(kxmh, kxml, vph, t1h, nullptr,
        nullptr, 128, 65536, 512, 8192, 16384, 0, 1048576, 1.0f, 1.0f);

    // join y, attend-y (+stats)
    cudaStreamWaitEvent(0, g_res.evY, 0);
    mma_kernel<0,0,3><<<dim3(64,1,32),256,SMEMB,0>>>(kymh, kyml, t1h, t2s, nullptr,
        sums, 128, 64, 8192, 0, 16384, 1048576, 0, 1.0f, 1.0f);

    // join sC (wo1h/wo2h ready), gelu GEMM: fused instance-norm, single-plane A
    cudaStreamWaitEvent(0, g_res.evQo, 0);
    mma_kernel<2,0,1><<<dim3(1,512,1),256,SMEMB,0>>>(t2s, nullptr, wo1h, goh, gol,
        sums, 512, 128, 64, 128, 0, 0, 0, S_GI, S_GO);
    // out = (go'@Wo2) * 2^-21 (2-plane A)
    mma_kernel<0,0,2><<<dim3(1,512,1),256,SMEMB,0>>>(goh, gol, wo2h, out, nullptr,
        nullptr, 128, 128, 64, 128, 0, 0, 0, 1.0f, S_OUT);
}